// round 3
// baseline (speedup 1.0000x reference)
#include <cuda_runtime.h>
#include <cuda_bf16.h>
#include <math.h>

// ---------------- problem constants ----------------
#define BB    32
#define NN    256
#define LL    1024
#define DIMD  128
#define MODEN 8
#define HH    4
#define DHD   32
#define FFD   256
#define MQ    (BB*LL)    // 32768 rows, q path
#define MP    (BB*NN)    // 8192 rows, phi path

// ---------------- scratch (device globals; no allocation allowed) ----------------
__device__ float g_X   [MQ * DIMD];
__device__ float g_X2  [MQ * DIMD];
__device__ float g_QKV [MQ * 3 * DIMD];
__device__ float g_CTX [MQ * DIMD];
__device__ float g_TMP [MQ * FFD];
__device__ float g_H1  [MP * DIMD];
__device__ float g_H2  [MP * DIMD];
__device__ float g_PHI [MP * MODEN];
__device__ float g_MAX [BB * MODEN];

// ---------------- helpers ----------------
__inline__ __device__ float warp_sum(float v) {
    #pragma unroll
    for (int o = 16; o > 0; o >>= 1) v += __shfl_xor_sync(0xffffffffu, v, o);
    return v;
}

// ---------------- proj_in: X[b*L+l, d] = sum_j acc_Y[b, 2+j, l]*w[d,j] + bias[d] ----------------
__global__ void proj_in_kernel(const float* __restrict__ Y,
                               const float* __restrict__ w,
                               const float* __restrict__ bias,
                               float* __restrict__ X) {
    int r = blockIdx.x;               // 0..MQ-1
    int b = r >> 10;
    int l = r & 1023;
    int t = threadIdx.x;              // 128
    __shared__ float xs[7];
    if (t < 7) xs[t] = Y[((size_t)b * NN + 2 + t) * LL + l];
    __syncthreads();
    float acc = bias[t];
    #pragma unroll
    for (int j = 0; j < 7; j++) acc += xs[j] * w[t * 7 + j];
    X[(size_t)r * DIMD + t] = acc;
}

// ---------------- generic tiled SGEMM: C[M,N] = A[M,K] @ W[N,K]^T + bias, activation ----------------
// ACT: 0 = none, 1 = relu, 2 = tanh.  Requires M%64==0, N%64==0, K%16==0.
template<int ACT>
__global__ __launch_bounds__(256) void gemm_kernel(const float* __restrict__ A,
                                                   const float* __restrict__ W,
                                                   const float* __restrict__ bias,
                                                   float* __restrict__ C,
                                                   int M, int N, int K) {
    __shared__ float As[16][68];
    __shared__ float Ws[16][68];
    int tid = threadIdx.x;
    int bm = blockIdx.y * 64;
    int bn = blockIdx.x * 64;
    int lr = tid >> 2;          // 0..63
    int lk = (tid & 3) * 4;     // 0,4,8,12
    int ty = tid >> 4;          // 0..15
    int tx = tid & 15;          // 0..15

    float acc[4][4];
    #pragma unroll
    for (int i = 0; i < 4; i++)
        #pragma unroll
        for (int j = 0; j < 4; j++) acc[i][j] = 0.f;

    for (int kt = 0; kt < K; kt += 16) {
        float4 a = *(const float4*)&A[(size_t)(bm + lr) * K + kt + lk];
        float4 w = *(const float4*)&W[(size_t)(bn + lr) * K + kt + lk];
        As[lk + 0][lr] = a.x; As[lk + 1][lr] = a.y; As[lk + 2][lr] = a.z; As[lk + 3][lr] = a.w;
        Ws[lk + 0][lr] = w.x; Ws[lk + 1][lr] = w.y; Ws[lk + 2][lr] = w.z; Ws[lk + 3][lr] = w.w;
        __syncthreads();
        #pragma unroll
        for (int k = 0; k < 16; k++) {
            float4 av = *(const float4*)&As[k][ty * 4];
            float4 wv = *(const float4*)&Ws[k][tx * 4];
            float am[4] = {av.x, av.y, av.z, av.w};
            float wn[4] = {wv.x, wv.y, wv.z, wv.w};
            #pragma unroll
            for (int i = 0; i < 4; i++)
                #pragma unroll
                for (int j = 0; j < 4; j++) acc[i][j] += am[i] * wn[j];
        }
        __syncthreads();
    }

    #pragma unroll
    for (int i = 0; i < 4; i++) {
        int row = bm + ty * 4 + i;
        float4 o;
        float v[4];
        #pragma unroll
        for (int j = 0; j < 4; j++) {
            float t = acc[i][j] + bias[bn + tx * 4 + j];
            if (ACT == 1) t = fmaxf(t, 0.f);
            if (ACT == 2) t = tanhf(t);
            v[j] = t;
        }
        o.x = v[0]; o.y = v[1]; o.z = v[2]; o.w = v[3];
        *(float4*)&C[(size_t)row * N + bn + tx * 4] = o;
    }
}

// ---------------- flash attention: per (q-block, head, batch) ----------------
// QKV layout: [B, L, 384] with q=[0,128), k=[128,256), v=[256,384); head h -> [h*32,(h+1)*32)
__global__ __launch_bounds__(128) void attn_kernel(const float* __restrict__ QKV,
                                                   float* __restrict__ CTX) {
    const float SCALE = 0.17677669529663687f; // 1/sqrt(32)
    int h = blockIdx.y;
    int b = blockIdx.z;
    int t = threadIdx.x;
    int qrow = blockIdx.x * 128 + t;
    const float* base = QKV + (size_t)b * LL * 384;

    float qv[32];
    {
        const float4* qp = (const float4*)(base + (size_t)qrow * 384 + h * 32);
        #pragma unroll
        for (int i = 0; i < 8; i++) {
            float4 f = qp[i];
            qv[i * 4 + 0] = f.x; qv[i * 4 + 1] = f.y; qv[i * 4 + 2] = f.z; qv[i * 4 + 3] = f.w;
        }
    }

    float o[32];
    #pragma unroll
    for (int d = 0; d < 32; d++) o[d] = 0.f;
    float mi = -1e30f, li = 0.f;

    __shared__ float Ks[32][32];
    __shared__ float Vs[32][32];

    for (int c = 0; c < LL / 32; c++) {
        // cooperative load of 32 keys/values (8 floats per thread each)
        int kr = c * 32 + (t >> 2);
        int seg = (t & 3) * 8;
        const float4* kp = (const float4*)(base + (size_t)kr * 384 + 128 + h * 32 + seg);
        const float4* vp = (const float4*)(base + (size_t)kr * 384 + 256 + h * 32 + seg);
        *(float4*)&Ks[t >> 2][seg]     = kp[0];
        *(float4*)&Ks[t >> 2][seg + 4] = kp[1];
        *(float4*)&Vs[t >> 2][seg]     = vp[0];
        *(float4*)&Vs[t >> 2][seg + 4] = vp[1];
        __syncthreads();

        float s[32];
        float cmax = -1e30f;
        #pragma unroll
        for (int m = 0; m < 32; m++) {
            float acc = 0.f;
            #pragma unroll
            for (int d4 = 0; d4 < 8; d4++) {
                float4 kk = *(const float4*)&Ks[m][d4 * 4];
                acc += qv[d4 * 4 + 0] * kk.x + qv[d4 * 4 + 1] * kk.y
                     + qv[d4 * 4 + 2] * kk.z + qv[d4 * 4 + 3] * kk.w;
            }
            s[m] = acc * SCALE;
            cmax = fmaxf(cmax, s[m]);
        }
        float nm = fmaxf(mi, cmax);
        float alpha = __expf(mi - nm);
        li *= alpha;
        #pragma unroll
        for (int d = 0; d < 32; d++) o[d] *= alpha;
        #pragma unroll
        for (int m = 0; m < 32; m++) {
            float p = __expf(s[m] - nm);
            li += p;
            #pragma unroll
            for (int d4 = 0; d4 < 8; d4++) {
                float4 vv = *(const float4*)&Vs[m][d4 * 4];
                o[d4 * 4 + 0] += p * vv.x; o[d4 * 4 + 1] += p * vv.y;
                o[d4 * 4 + 2] += p * vv.z; o[d4 * 4 + 3] += p * vv.w;
            }
        }
        mi = nm;
        __syncthreads();
    }

    float inv = 1.f / li;
    float* op = CTX + ((size_t)(b * LL + qrow)) * DIMD + h * 32;
    #pragma unroll
    for (int d4 = 0; d4 < 8; d4++) {
        float4 f;
        f.x = o[d4 * 4 + 0] * inv; f.y = o[d4 * 4 + 1] * inv;
        f.z = o[d4 * 4 + 2] * inv; f.w = o[d4 * 4 + 3] * inv;
        *(float4*)&op[d4 * 4] = f;
    }
}

// ---------------- residual + layernorm over DIM=128 ----------------
__global__ void ln_kernel(const float* __restrict__ x, const float* __restrict__ res,
                          const float* __restrict__ g, const float* __restrict__ b,
                          float* __restrict__ out) {
    int r = blockIdx.x;
    int t = threadIdx.x; // 128
    size_t idx = (size_t)r * DIMD + t;
    float v = x[idx] + res[idx];
    __shared__ float red[8];
    float s1 = warp_sum(v);
    float s2 = warp_sum(v * v);
    if ((t & 31) == 0) { red[t >> 5] = s1; red[4 + (t >> 5)] = s2; }
    __syncthreads();
    float sum   = red[0] + red[1] + red[2] + red[3];
    float sumsq = red[4] + red[5] + red[6] + red[7];
    float mean = sum * (1.0f / 128.0f);
    float var  = sumsq * (1.0f / 128.0f) - mean * mean;
    out[idx] = (v - mean) * rsqrtf(var + 1e-5f) * g[t] + b[t];
}

// ---------------- small-N GEMM: C[M,8] = A[M,128] @ W[8,128]^T + bias ----------------
__global__ __launch_bounds__(256) void gemm_n8(const float* __restrict__ A,
                                               const float* __restrict__ W,
                                               const float* __restrict__ bias,
                                               float* __restrict__ C) {
    __shared__ float As[32][128];
    __shared__ float Ws[8][128];
    int tid = threadIdx.x;
    size_t row0 = (size_t)blockIdx.x * 32;
    ((float4*)Ws)[tid] = ((const float4*)W)[tid];  // 8*128 floats = 256 float4
    const float4* A4 = (const float4*)(A + row0 * 128);
    #pragma unroll
    for (int s = 0; s < 4; s++) ((float4*)As)[tid + s * 256] = A4[tid + s * 256];
    __syncthreads();
    int r = tid >> 3, j = tid & 7;
    float acc = 0.f;
    #pragma unroll
    for (int k4 = 0; k4 < 32; k4++) {
        float4 a = ((const float4*)As[r])[k4];
        float4 w = ((const float4*)Ws[j])[k4];
        acc += a.x * w.x + a.y * w.y + a.z * w.z + a.w * w.w;
    }
    C[(row0 + r) * MODEN + j] = acc + bias[j];
}

// ---------------- per-(b, mode) max-abs over N nodes ----------------
__global__ void maxabs_kernel(const float* __restrict__ phi, float* __restrict__ gmax) {
    int b = blockIdx.x;
    int n = threadIdx.x; // 256
    __shared__ float sm[256][8];
    #pragma unroll
    for (int j = 0; j < 8; j++)
        sm[n][j] = fabsf(phi[((size_t)b * NN + n) * MODEN + j]);
    __syncthreads();
    for (int s = 128; s > 0; s >>= 1) {
        if (n < s) {
            #pragma unroll
            for (int j = 0; j < 8; j++) sm[n][j] = fmaxf(sm[n][j], sm[n + s][j]);
        }
        __syncthreads();
    }
    if (n < 8) gmax[b * 8 + n] = sm[0][n];
}

__global__ void phinorm_kernel(const float* __restrict__ phi, const float* __restrict__ gmax,
                               float* __restrict__ out) {
    int i = blockIdx.x * 256 + threadIdx.x; // MP*MODEN = 65536
    int b = i >> 11;     // NN*MODEN = 2048 per batch
    int j = i & 7;
    out[i] = phi[i] / gmax[b * 8 + j];
}

// ---------------- launch ----------------
extern "C" void kernel_launch(void* const* d_in, const int* in_sizes, int n_in,
                              void* d_out, int out_size) {
    (void)in_sizes; (void)n_in; (void)out_size;
    const float* acc_Y      = (const float*)d_in[0];
    const float* proj_in_w  = (const float*)d_in[2];
    const float* proj_in_b  = (const float*)d_in[3];
    const float* attn_in_w  = (const float*)d_in[4];
    const float* attn_in_b  = (const float*)d_in[5];
    const float* attn_out_w = (const float*)d_in[6];
    const float* attn_out_b = (const float*)d_in[7];
    const float* ln1_g      = (const float*)d_in[8];
    const float* ln1_b      = (const float*)d_in[9];
    const float* ff1_w      = (const float*)d_in[10];
    const float* ff1_b      = (const float*)d_in[11];
    const float* ff2_w      = (const float*)d_in[12];
    const float* ff2_b      = (const float*)d_in[13];
    const float* ln2_g      = (const float*)d_in[14];
    const float* ln2_b      = (const float*)d_in[15];
    const float* proj_out_w = (const float*)d_in[16];
    const float* proj_out_b = (const float*)d_in[17];
    const float* mlp1_w     = (const float*)d_in[18];
    const float* mlp1_b     = (const float*)d_in[19];
    const float* mlp2_w     = (const float*)d_in[20];
    const float* mlp2_b     = (const float*)d_in[21];
    const float* mlp3_w     = (const float*)d_in[22];
    const float* mlp3_b     = (const float*)d_in[23];
    float* out = (float*)d_out;

    float *pX, *pX2, *pQKV, *pCTX, *pTMP, *pH1, *pH2, *pPHI, *pMAX;
    cudaGetSymbolAddress((void**)&pX,   g_X);
    cudaGetSymbolAddress((void**)&pX2,  g_X2);
    cudaGetSymbolAddress((void**)&pQKV, g_QKV);
    cudaGetSymbolAddress((void**)&pCTX, g_CTX);
    cudaGetSymbolAddress((void**)&pTMP, g_TMP);
    cudaGetSymbolAddress((void**)&pH1,  g_H1);
    cudaGetSymbolAddress((void**)&pH2,  g_H2);
    cudaGetSymbolAddress((void**)&pPHI, g_PHI);
    cudaGetSymbolAddress((void**)&pMAX, g_MAX);

    // ===== q path =====
    proj_in_kernel<<<MQ, 128>>>(acc_Y, proj_in_w, proj_in_b, pX);
    gemm_kernel<0><<<dim3(384 / 64, MQ / 64), 256>>>(pX, attn_in_w, attn_in_b, pQKV, MQ, 384, 128);
    attn_kernel<<<dim3(LL / 128, HH, BB), 128>>>(pQKV, pCTX);
    gemm_kernel<0><<<dim3(128 / 64, MQ / 64), 256>>>(pCTX, attn_out_w, attn_out_b, pTMP, MQ, 128, 128);
    ln_kernel<<<MQ, 128>>>(pX, pTMP, ln1_g, ln1_b, pX2);
    gemm_kernel<1><<<dim3(256 / 64, MQ / 64), 256>>>(pX2, ff1_w, ff1_b, pTMP, MQ, 256, 128);
    gemm_kernel<0><<<dim3(128 / 64, MQ / 64), 256>>>(pTMP, ff2_w, ff2_b, pCTX, MQ, 128, 256);
    ln_kernel<<<MQ, 128>>>(pX2, pCTX, ln2_g, ln2_b, pX);
    gemm_n8<<<MQ / 32, 256>>>(pX, proj_out_w, proj_out_b, out);   // q -> out[0 : 262144)

    // ===== phi path =====
    gemm_kernel<2><<<dim3(128 / 64, MP / 64), 256>>>(acc_Y, mlp1_w, mlp1_b, pH1, MP, 128, 1024);
    gemm_kernel<2><<<dim3(128 / 64, MP / 64), 256>>>(pH1, mlp2_w, mlp2_b, pH2, MP, 128, 128);
    gemm_kernel<2><<<dim3(128 / 64, MP / 64), 256>>>(pH2, mlp2_w, mlp2_b, pH1, MP, 128, 128);
    gemm_n8<<<MP / 32, 256>>>(pH1, mlp3_w, mlp3_b, pPHI);
    maxabs_kernel<<<BB, 256>>>(pPHI, pMAX);
    phinorm_kernel<<<(MP * MODEN) / 256, 256>>>(pPHI, pMAX, out + MQ * MODEN);
}

// round 6
// speedup vs baseline: 1.9309x; 1.9309x over previous
#include <cuda_runtime.h>
#include <cuda_fp16.h>
#include <cuda_bf16.h>
#include <math.h>
#include <stdint.h>

// ---------------- problem constants ----------------
#define BB    32
#define NN    256
#define LL    1024
#define DIMD  128
#define MODEN 8
#define HH    4
#define DHD   32
#define FFD   256
#define MQ    (BB*LL)    // 32768 rows, q path
#define MP    (BB*NN)    // 8192 rows, phi path
#define ATTN_SCALE 0.17677669529663687f  // 1/sqrt(32)

// ---------------- scratch (device globals; no allocation allowed) ----------------
__device__ float g_X   [MQ * DIMD];
__device__ float g_X2  [MQ * DIMD];
__device__ float g_QKV [MQ * 3 * DIMD];
__device__ float g_CTX [MQ * DIMD];
__device__ float g_TMP [MQ * FFD];
__device__ float g_H1  [MP * DIMD];
__device__ float g_H2  [MP * DIMD];
__device__ float g_PHI [MP * MODEN];
__device__ float g_MAX [BB * MODEN];

// ---------------- helpers ----------------
__inline__ __device__ float warp_sum(float v) {
    #pragma unroll
    for (int o = 16; o > 0; o >>= 1) v += __shfl_xor_sync(0xffffffffu, v, o);
    return v;
}

__device__ __forceinline__ uint32_t smem_u32(const void* p) {
    return (uint32_t)__cvta_generic_to_shared(p);
}

__device__ __forceinline__ uint32_t f2h2(float a, float b) {
    __half2 h = __floats2half2_rn(a, b);
    return *reinterpret_cast<uint32_t*>(&h);
}

#define LDSM4(r0,r1,r2,r3,addr) \
    asm volatile("ldmatrix.sync.aligned.m8n8.x4.shared.b16 {%0,%1,%2,%3},[%4];" \
                 : "=r"(r0),"=r"(r1),"=r"(r2),"=r"(r3) : "r"(addr))
#define LDSM4T(r0,r1,r2,r3,addr) \
    asm volatile("ldmatrix.sync.aligned.m8n8.x4.trans.shared.b16 {%0,%1,%2,%3},[%4];" \
                 : "=r"(r0),"=r"(r1),"=r"(r2),"=r"(r3) : "r"(addr))
#define MMA16816(c,a0,a1,a2,a3,b0,b1) \
    asm volatile("mma.sync.aligned.m16n8k16.row.col.f32.f16.f16.f32 " \
                 "{%0,%1,%2,%3},{%4,%5,%6,%7},{%8,%9},{%0,%1,%2,%3};" \
                 : "+f"(c[0]),"+f"(c[1]),"+f"(c[2]),"+f"(c[3]) \
                 : "r"(a0),"r"(a1),"r"(a2),"r"(a3),"r"(b0),"r"(b1))

// ---------------- proj_in: X[b*L+l, d] = sum_j acc_Y[b, 2+j, l]*w[d,j] + bias[d] ----------------
__global__ void proj_in_kernel(const float* __restrict__ Y,
                               const float* __restrict__ w,
                               const float* __restrict__ bias,
                               float* __restrict__ X) {
    int r = blockIdx.x;               // 0..MQ-1
    int b = r >> 10;
    int l = r & 1023;
    int t = threadIdx.x;              // 128
    __shared__ float xs[7];
    if (t < 7) xs[t] = Y[((size_t)b * NN + 2 + t) * LL + l];
    __syncthreads();
    float acc = bias[t];
    #pragma unroll
    for (int j = 0; j < 7; j++) acc += xs[j] * w[t * 7 + j];
    X[(size_t)r * DIMD + t] = acc;
}

// ---------------- big tiled SGEMM: 128x128 tile, 8x8 per thread ----------------
// C[M,N] = A[M,K] @ W[N,K]^T + bias, ACT: 0 none, 1 relu
// Requires M%128==0, N%128==0, K%8==0.
template<int ACT>
__global__ __launch_bounds__(256) void gemm128_kernel(const float* __restrict__ A,
                                                      const float* __restrict__ W,
                                                      const float* __restrict__ bias,
                                                      float* __restrict__ C,
                                                      int M, int N, int K) {
    __shared__ float As[8][132];
    __shared__ float Ws[8][132];
    int tid = threadIdx.x;
    int bm = blockIdx.y * 128;
    int bn = blockIdx.x * 128;
    int lrow = tid >> 1;            // 0..127
    int lk   = (tid & 1) * 4;       // 0 or 4
    int ry   = (tid >> 4) * 4;      // 0..60
    int rx   = (tid & 15) * 4;      // 0..60

    float acc[8][8];
    #pragma unroll
    for (int i = 0; i < 8; i++)
        #pragma unroll
        for (int j = 0; j < 8; j++) acc[i][j] = 0.f;

    for (int kt = 0; kt < K; kt += 8) {
        float4 a  = *(const float4*)&A[(size_t)(bm + lrow) * K + kt + lk];
        float4 wv = *(const float4*)&W[(size_t)(bn + lrow) * K + kt + lk];
        As[lk + 0][lrow] = a.x;  As[lk + 1][lrow] = a.y;
        As[lk + 2][lrow] = a.z;  As[lk + 3][lrow] = a.w;
        Ws[lk + 0][lrow] = wv.x; Ws[lk + 1][lrow] = wv.y;
        Ws[lk + 2][lrow] = wv.z; Ws[lk + 3][lrow] = wv.w;
        __syncthreads();
        #pragma unroll
        for (int k = 0; k < 8; k++) {
            float4 a0 = *(const float4*)&As[k][ry];
            float4 a1 = *(const float4*)&As[k][ry + 64];
            float4 w0 = *(const float4*)&Ws[k][rx];
            float4 w1 = *(const float4*)&Ws[k][rx + 64];
            float ar[8] = {a0.x, a0.y, a0.z, a0.w, a1.x, a1.y, a1.z, a1.w};
            float wr[8] = {w0.x, w0.y, w0.z, w0.w, w1.x, w1.y, w1.z, w1.w};
            #pragma unroll
            for (int i = 0; i < 8; i++)
                #pragma unroll
                for (int j = 0; j < 8; j++) acc[i][j] += ar[i] * wr[j];
        }
        __syncthreads();
    }

    float4 bv0 = *(const float4*)&bias[bn + rx];
    float4 bv1 = *(const float4*)&bias[bn + rx + 64];
    float bb0[8] = {bv0.x, bv0.y, bv0.z, bv0.w, bv1.x, bv1.y, bv1.z, bv1.w};
    #pragma unroll
    for (int i = 0; i < 8; i++) {
        int row = bm + ry + ((i < 4) ? i : (60 + i));
        float v[8];
        #pragma unroll
        for (int j = 0; j < 8; j++) {
            float tv = acc[i][j] + bb0[j];
            if (ACT == 1) tv = fmaxf(tv, 0.f);
            v[j] = tv;
        }
        *(float4*)&C[(size_t)row * N + bn + rx]      = make_float4(v[0], v[1], v[2], v[3]);
        *(float4*)&C[(size_t)row * N + bn + rx + 64] = make_float4(v[4], v[5], v[6], v[7]);
    }
}

// ---------------- legacy 64x64 SGEMM (phi path; better block count at M=8192) ----------------
// ACT: 0 none, 1 relu, 2 tanh. Requires M%64==0, N%64==0, K%16==0.
template<int ACT>
__global__ __launch_bounds__(256) void gemm_kernel(const float* __restrict__ A,
                                                   const float* __restrict__ W,
                                                   const float* __restrict__ bias,
                                                   float* __restrict__ C,
                                                   int M, int N, int K) {
    __shared__ float As[16][68];
    __shared__ float Ws[16][68];
    int tid = threadIdx.x;
    int bm = blockIdx.y * 64;
    int bn = blockIdx.x * 64;
    int lr = tid >> 2;
    int lk = (tid & 3) * 4;
    int ty = tid >> 4;
    int tx = tid & 15;

    float acc[4][4];
    #pragma unroll
    for (int i = 0; i < 4; i++)
        #pragma unroll
        for (int j = 0; j < 4; j++) acc[i][j] = 0.f;

    for (int kt = 0; kt < K; kt += 16) {
        float4 a = *(const float4*)&A[(size_t)(bm + lr) * K + kt + lk];
        float4 w = *(const float4*)&W[(size_t)(bn + lr) * K + kt + lk];
        As[lk + 0][lr] = a.x; As[lk + 1][lr] = a.y; As[lk + 2][lr] = a.z; As[lk + 3][lr] = a.w;
        Ws[lk + 0][lr] = w.x; Ws[lk + 1][lr] = w.y; Ws[lk + 2][lr] = w.z; Ws[lk + 3][lr] = w.w;
        __syncthreads();
        #pragma unroll
        for (int k = 0; k < 16; k++) {
            float4 av = *(const float4*)&As[k][ty * 4];
            float4 wv = *(const float4*)&Ws[k][tx * 4];
            float am[4] = {av.x, av.y, av.z, av.w};
            float wn[4] = {wv.x, wv.y, wv.z, wv.w};
            #pragma unroll
            for (int i = 0; i < 4; i++)
                #pragma unroll
                for (int j = 0; j < 4; j++) acc[i][j] += am[i] * wn[j];
        }
        __syncthreads();
    }

    #pragma unroll
    for (int i = 0; i < 4; i++) {
        int row = bm + ty * 4 + i;
        float v[4];
        #pragma unroll
        for (int j = 0; j < 4; j++) {
            float t = acc[i][j] + bias[bn + tx * 4 + j];
            if (ACT == 1) t = fmaxf(t, 0.f);
            if (ACT == 2) t = tanhf(t);
            v[j] = t;
        }
        *(float4*)&C[(size_t)row * N + bn + tx * 4] = make_float4(v[0], v[1], v[2], v[3]);
    }
}

// ---------------- fp16 tensor-core flash attention ----------------
// QKV layout: [B, L, 384] q=[0,128) k=[128,256) v=[256,384); head h -> [h*32,(h+1)*32)
// Block: 128 queries (8 warps x 16), loops 16 key-tiles of 64.
// grid (L/128, H, B), 256 threads.
__global__ __launch_bounds__(256) void attn_mma_kernel(const float* __restrict__ QKV,
                                                       float* __restrict__ CTX) {
    int h = blockIdx.y;
    int b = blockIdx.z;
    int qbase = blockIdx.x * 128;
    int t = threadIdx.x;
    int w = t >> 5, lane = t & 31;

    __shared__ __half Qs[128][40];
    __shared__ __half Ks[64][40];
    __shared__ __half Vs[64][40];

    const float* base = QKV + (size_t)b * (LL * 384);

    // ---- load Q tile (scaled), fp32 -> fp16 ----
    {
        int row = t >> 1, c0 = (t & 1) * 16;
        const float4* src = (const float4*)(base + (size_t)(qbase + row) * 384 + h * 32 + c0);
        __half2* dst = (__half2*)&Qs[row][c0];
        #pragma unroll
        for (int i = 0; i < 4; i++) {
            float4 f = src[i];
            dst[2 * i]     = __floats2half2_rn(f.x * ATTN_SCALE, f.y * ATTN_SCALE);
            dst[2 * i + 1] = __floats2half2_rn(f.z * ATTN_SCALE, f.w * ATTN_SCALE);
        }
    }
    __syncthreads();

    // ---- Q fragments: A operand m16k16 x2 (k = 0..15, 16..31) ----
    uint32_t qa[2][4];
    {
        int qr = w * 16;
        #pragma unroll
        for (int s = 0; s < 2; s++) {
            int row = qr + (lane & 15);
            int col = s * 16 + (lane >> 4) * 8;
            uint32_t addr = smem_u32(&Qs[row][col]);
            LDSM4(qa[s][0], qa[s][1], qa[s][2], qa[s][3], addr);
        }
    }

    float oacc[4][4];
    #pragma unroll
    for (int j = 0; j < 4; j++)
        #pragma unroll
        for (int c = 0; c < 4; c++) oacc[j][c] = 0.f;
    float mrun0 = -1e30f, mrun1 = -1e30f, l0 = 0.f, l1 = 0.f;

    for (int kt = 0; kt < 16; kt++) {
        // ---- cooperative K/V tile load (warps 0-3: K, 4-7: V) ----
        {
            int tt = t & 127;
            int row = tt >> 1, c0 = (tt & 1) * 16;
            int off = (t < 128) ? 128 : 256;
            const float4* src = (const float4*)(base + (size_t)(kt * 64 + row) * 384 + off + h * 32 + c0);
            __half2* dst = (t < 128) ? (__half2*)&Ks[row][c0] : (__half2*)&Vs[row][c0];
            #pragma unroll
            for (int i = 0; i < 4; i++) {
                float4 f = src[i];
                dst[2 * i]     = __floats2half2_rn(f.x, f.y);
                dst[2 * i + 1] = __floats2half2_rn(f.z, f.w);
            }
        }
        __syncthreads();

        // ---- S = Q K^T : 8 n-blocks of 8 keys ----
        float sacc[8][4];
        #pragma unroll
        for (int j = 0; j < 8; j++)
            #pragma unroll
            for (int c = 0; c < 4; c++) sacc[j][c] = 0.f;

        #pragma unroll
        for (int j = 0; j < 8; j++) {
            uint32_t kb[4];
            uint32_t addr = smem_u32(&Ks[8 * j + (lane & 7)][(lane >> 3) * 8]);
            LDSM4(kb[0], kb[1], kb[2], kb[3], addr);  // kb[0..1]=k-step0, kb[2..3]=k-step1
            MMA16816(sacc[j], qa[0][0], qa[0][1], qa[0][2], qa[0][3], kb[0], kb[1]);
            MMA16816(sacc[j], qa[1][0], qa[1][1], qa[1][2], qa[1][3], kb[2], kb[3]);
        }

        // ---- online softmax (rows lane>>2 and lane>>2 + 8) ----
        float mx0 = -1e30f, mx1 = -1e30f;
        #pragma unroll
        for (int j = 0; j < 8; j++) {
            mx0 = fmaxf(mx0, fmaxf(sacc[j][0], sacc[j][1]));
            mx1 = fmaxf(mx1, fmaxf(sacc[j][2], sacc[j][3]));
        }
        #pragma unroll
        for (int o = 1; o <= 2; o <<= 1) {
            mx0 = fmaxf(mx0, __shfl_xor_sync(0xffffffffu, mx0, o));
            mx1 = fmaxf(mx1, __shfl_xor_sync(0xffffffffu, mx1, o));
        }
        float nm0 = fmaxf(mrun0, mx0), nm1 = fmaxf(mrun1, mx1);
        float al0 = __expf(mrun0 - nm0), al1 = __expf(mrun1 - nm1);
        mrun0 = nm0; mrun1 = nm1;

        float rs0 = 0.f, rs1 = 0.f;
        #pragma unroll
        for (int j = 0; j < 8; j++) {
            sacc[j][0] = __expf(sacc[j][0] - nm0); rs0 += sacc[j][0];
            sacc[j][1] = __expf(sacc[j][1] - nm0); rs0 += sacc[j][1];
            sacc[j][2] = __expf(sacc[j][2] - nm1); rs1 += sacc[j][2];
            sacc[j][3] = __expf(sacc[j][3] - nm1); rs1 += sacc[j][3];
        }
        #pragma unroll
        for (int o = 1; o <= 2; o <<= 1) {
            rs0 += __shfl_xor_sync(0xffffffffu, rs0, o);
            rs1 += __shfl_xor_sync(0xffffffffu, rs1, o);
        }
        l0 = l0 * al0 + rs0;
        l1 = l1 * al1 + rs1;
        #pragma unroll
        for (int j = 0; j < 4; j++) {
            oacc[j][0] *= al0; oacc[j][1] *= al0;
            oacc[j][2] *= al1; oacc[j][3] *= al1;
        }

        // ---- O += P V : 4 k-steps of 16 keys, n-blocks = dims ----
        #pragma unroll
        for (int s = 0; s < 4; s++) {
            uint32_t pa0 = f2h2(sacc[2 * s][0], sacc[2 * s][1]);
            uint32_t pa1 = f2h2(sacc[2 * s][2], sacc[2 * s][3]);
            uint32_t pa2 = f2h2(sacc[2 * s + 1][0], sacc[2 * s + 1][1]);
            uint32_t pa3 = f2h2(sacc[2 * s + 1][2], sacc[2 * s + 1][3]);
            #pragma unroll
            for (int jj = 0; jj < 2; jj++) {
                uint32_t vb[4];
                uint32_t addr = smem_u32(&Vs[16 * s + (lane & 15)][8 * (2 * jj + (lane >> 4))]);
                LDSM4T(vb[0], vb[1], vb[2], vb[3], addr);
                MMA16816(oacc[2 * jj],     pa0, pa1, pa2, pa3, vb[0], vb[1]);
                MMA16816(oacc[2 * jj + 1], pa0, pa1, pa2, pa3, vb[2], vb[3]);
            }
        }
        __syncthreads();
    }

    // ---- epilogue ----
    float inv0 = 1.f / l0, inv1 = 1.f / l1;
    int r0 = qbase + w * 16 + (lane >> 2);
    float* o0 = CTX + ((size_t)(b * LL + r0)) * DIMD + h * 32 + 2 * (lane & 3);
    float* o1 = o0 + 8 * DIMD;
    #pragma unroll
    for (int j = 0; j < 4; j++) {
        *(float2*)(o0 + 8 * j) = make_float2(oacc[j][0] * inv0, oacc[j][1] * inv0);
        *(float2*)(o1 + 8 * j) = make_float2(oacc[j][2] * inv1, oacc[j][3] * inv1);
    }
}

// ---------------- residual + layernorm over DIM=128 ----------------
__global__ void ln_kernel(const float* __restrict__ x, const float* __restrict__ res,
                          const float* __restrict__ g, const float* __restrict__ b,
                          float* __restrict__ out) {
    int r = blockIdx.x;
    int t = threadIdx.x; // 128
    size_t idx = (size_t)r * DIMD + t;
    float v = x[idx] + res[idx];
    __shared__ float red[8];
    float s1 = warp_sum(v);
    float s2 = warp_sum(v * v);
    if ((t & 31) == 0) { red[t >> 5] = s1; red[4 + (t >> 5)] = s2; }
    __syncthreads();
    float sum   = red[0] + red[1] + red[2] + red[3];
    float sumsq = red[4] + red[5] + red[6] + red[7];
    float mean = sum * (1.0f / 128.0f);
    float var  = sumsq * (1.0f / 128.0f) - mean * mean;
    out[idx] = (v - mean) * rsqrtf(var + 1e-5f) * g[t] + b[t];
}

// ---------------- small-N GEMM: C[M,8] = A[M,128] @ W[8,128]^T + bias ----------------
__global__ __launch_bounds__(256) void gemm_n8(const float* __restrict__ A,
                                               const float* __restrict__ W,
                                               const float* __restrict__ bias,
                                               float* __restrict__ C) {
    __shared__ float As[32][128];
    __shared__ float Ws[8][128];
    int tid = threadIdx.x;
    size_t row0 = (size_t)blockIdx.x * 32;
    ((float4*)Ws)[tid] = ((const float4*)W)[tid];
    const float4* A4 = (const float4*)(A + row0 * 128);
    #pragma unroll
    for (int s = 0; s < 4; s++) ((float4*)As)[tid + s * 256] = A4[tid + s * 256];
    __syncthreads();
    int r = tid >> 3, j = tid & 7;
    float acc = 0.f;
    #pragma unroll
    for (int k4 = 0; k4 < 32; k4++) {
        float4 a = ((const float4*)As[r])[k4];
        float4 w = ((const float4*)Ws[j])[k4];
        acc += a.x * w.x + a.y * w.y + a.z * w.z + a.w * w.w;
    }
    C[(row0 + r) * MODEN + j] = acc + bias[j];
}

// ---------------- per-(b, mode) max-abs over N nodes ----------------
__global__ void maxabs_kernel(const float* __restrict__ phi, float* __restrict__ gmax) {
    int b = blockIdx.x;
    int n = threadIdx.x; // 256
    __shared__ float sm[256][8];
    #pragma unroll
    for (int j = 0; j < 8; j++)
        sm[n][j] = fabsf(phi[((size_t)b * NN + n) * MODEN + j]);
    __syncthreads();
    for (int s = 128; s > 0; s >>= 1) {
        if (n < s) {
            #pragma unroll
            for (int j = 0; j < 8; j++) sm[n][j] = fmaxf(sm[n][j], sm[n + s][j]);
        }
        __syncthreads();
    }
    if (n < 8) gmax[b * 8 + n] = sm[0][n];
}

__global__ void phinorm_kernel(const float* __restrict__ phi, const float* __restrict__ gmax,
                               float* __restrict__ out) {
    int i = blockIdx.x * 256 + threadIdx.x; // MP*MODEN = 65536
    int b = i >> 11;
    int j = i & 7;
    out[i] = phi[i] / gmax[b * 8 + j];
}

// ---------------- launch ----------------
extern "C" void kernel_launch(void* const* d_in, const int* in_sizes, int n_in,
                              void* d_out, int out_size) {
    (void)in_sizes; (void)n_in; (void)out_size;
    const float* acc_Y      = (const float*)d_in[0];
    const float* proj_in_w  = (const float*)d_in[2];
    const float* proj_in_b  = (const float*)d_in[3];
    const float* attn_in_w  = (const float*)d_in[4];
    const float* attn_in_b  = (const float*)d_in[5];
    const float* attn_out_w = (const float*)d_in[6];
    const float* attn_out_b = (const float*)d_in[7];
    const float* ln1_g      = (const float*)d_in[8];
    const float* ln1_b      = (const float*)d_in[9];
    const float* ff1_w      = (const float*)d_in[10];
    const float* ff1_b      = (const float*)d_in[11];
    const float* ff2_w      = (const float*)d_in[12];
    const float* ff2_b      = (const float*)d_in[13];
    const float* ln2_g      = (const float*)d_in[14];
    const float* ln2_b      = (const float*)d_in[15];
    const float* proj_out_w = (const float*)d_in[16];
    const float* proj_out_b = (const float*)d_in[17];
    const float* mlp1_w     = (const float*)d_in[18];
    const float* mlp1_b     = (const float*)d_in[19];
    const float* mlp2_w     = (const float*)d_in[20];
    const float* mlp2_b     = (const float*)d_in[21];
    const float* mlp3_w     = (const float*)d_in[22];
    const float* mlp3_b     = (const float*)d_in[23];
    float* out = (float*)d_out;

    float *pX, *pX2, *pQKV, *pCTX, *pTMP, *pH1, *pH2, *pPHI, *pMAX;
    cudaGetSymbolAddress((void**)&pX,   g_X);
    cudaGetSymbolAddress((void**)&pX2,  g_X2);
    cudaGetSymbolAddress((void**)&pQKV, g_QKV);
    cudaGetSymbolAddress((void**)&pCTX, g_CTX);
    cudaGetSymbolAddress((void**)&pTMP, g_TMP);
    cudaGetSymbolAddress((void**)&pH1,  g_H1);
    cudaGetSymbolAddress((void**)&pH2,  g_H2);
    cudaGetSymbolAddress((void**)&pPHI, g_PHI);
    cudaGetSymbolAddress((void**)&pMAX, g_MAX);

    // ===== q path =====
    proj_in_kernel<<<MQ, 128>>>(acc_Y, proj_in_w, proj_in_b, pX);
    gemm128_kernel<0><<<dim3(3, MQ / 128), 256>>>(pX, attn_in_w, attn_in_b, pQKV, MQ, 384, 128);
    attn_mma_kernel<<<dim3(LL / 128, HH, BB), 256>>>(pQKV, pCTX);
    gemm128_kernel<0><<<dim3(1, MQ / 128), 256>>>(pCTX, attn_out_w, attn_out_b, pTMP, MQ, 128, 128);
    ln_kernel<<<MQ, 128>>>(pX, pTMP, ln1_g, ln1_b, pX2);
    gemm128_kernel<1><<<dim3(2, MQ / 128), 256>>>(pX2, ff1_w, ff1_b, pTMP, MQ, 256, 128);
    gemm128_kernel<0><<<dim3(1, MQ / 128), 256>>>(pTMP, ff2_w, ff2_b, pCTX, MQ, 128, 256);
    ln_kernel<<<MQ, 128>>>(pX2, pCTX, ln2_g, ln2_b, pX);
    gemm_n8<<<MQ / 32, 256>>>(pX, proj_out_w, proj_out_b, out);   // q -> out[0 : 262144)

    // ===== phi path =====
    gemm_kernel<2><<<dim3(128 / 64, MP / 64), 256>>>(acc_Y, mlp1_w, mlp1_b, pH1, MP, 128, 1024);
    gemm_kernel<2><<<dim3(128 / 64, MP / 64), 256>>>(pH1, mlp2_w, mlp2_b, pH2, MP, 128, 128);
    gemm_kernel<2><<<dim3(128 / 64, MP / 64), 256>>>(pH2, mlp2_w, mlp2_b, pH1, MP, 128, 128);
    gemm_n8<<<MP / 32, 256>>>(pH1, mlp3_w, mlp3_b, pPHI);
    maxabs_kernel<<<BB, 256>>>(pPHI, pMAX);
    phinorm_kernel<<<(MP * MODEN) / 256, 256>>>(pPHI, pMAX, out + MQ * MODEN);
}

// round 8
// speedup vs baseline: 3.1160x; 1.6137x over previous
#include <cuda_runtime.h>
#include <cuda_fp16.h>
#include <cuda_bf16.h>
#include <math.h>
#include <stdint.h>

// ---------------- problem constants ----------------
#define BB    32
#define NN    256
#define LL    1024
#define DIMD  128
#define MODEN 8
#define HH    4
#define DHD   32
#define FFD   256
#define MQ    (BB*LL)    // 32768 rows, q path
#define MP    (BB*NN)    // 8192 rows, phi path
#define ATTN_SCALE 0.17677669529663687f  // 1/sqrt(32)

// ---------------- scratch (device globals; no allocation allowed) ----------------
__device__ float g_X   [MQ * DIMD];
__device__ float g_X2  [MQ * DIMD];
__device__ float g_QKV [MQ * 3 * DIMD];
__device__ float g_CTX [MQ * DIMD];
__device__ float g_TMP [MQ * FFD];
__device__ float g_H1  [MP * DIMD];
__device__ float g_H2  [MP * DIMD];
__device__ float g_PHI [MP * MODEN];
__device__ float g_MAX [BB * MODEN];

// ---------------- helpers ----------------
__inline__ __device__ float warp_sum(float v) {
    #pragma unroll
    for (int o = 16; o > 0; o >>= 1) v += __shfl_xor_sync(0xffffffffu, v, o);
    return v;
}

__device__ __forceinline__ uint32_t smem_u32(const void* p) {
    return (uint32_t)__cvta_generic_to_shared(p);
}

__device__ __forceinline__ uint32_t f2h2(float a, float b) {
    __half2 h = __floats2half2_rn(a, b);
    return *reinterpret_cast<uint32_t*>(&h);
}

#define LDSM4(r0,r1,r2,r3,addr) \
    asm volatile("ldmatrix.sync.aligned.m8n8.x4.shared.b16 {%0,%1,%2,%3},[%4];" \
                 : "=r"(r0),"=r"(r1),"=r"(r2),"=r"(r3) : "r"(addr))
#define LDSM4T(r0,r1,r2,r3,addr) \
    asm volatile("ldmatrix.sync.aligned.m8n8.x4.trans.shared.b16 {%0,%1,%2,%3},[%4];" \
                 : "=r"(r0),"=r"(r1),"=r"(r2),"=r"(r3) : "r"(addr))
#define MMA16816(c,a0,a1,a2,a3,b0,b1) \
    asm volatile("mma.sync.aligned.m16n8k16.row.col.f32.f16.f16.f32 " \
                 "{%0,%1,%2,%3},{%4,%5,%6,%7},{%8,%9},{%0,%1,%2,%3};" \
                 : "+f"(c[0]),"+f"(c[1]),"+f"(c[2]),"+f"(c[3]) \
                 : "r"(a0),"r"(a1),"r"(a2),"r"(a3),"r"(b0),"r"(b1))

// ---------------- proj_in: X[b*L+l, d] = sum_j acc_Y[b, 2+j, l]*w[d,j] + bias[d] ----------------
__global__ void proj_in_kernel(const float* __restrict__ Y,
                               const float* __restrict__ w,
                               const float* __restrict__ bias,
                               float* __restrict__ X) {
    int r = blockIdx.x;               // 0..MQ-1
    int b = r >> 10;
    int l = r & 1023;
    int t = threadIdx.x;              // 128
    __shared__ float xs[7];
    if (t < 7) xs[t] = Y[((size_t)b * NN + 2 + t) * LL + l];
    __syncthreads();
    float acc = bias[t];
    #pragma unroll
    for (int j = 0; j < 7; j++) acc += xs[j] * w[t * 7 + j];
    X[(size_t)r * DIMD + t] = acc;
}

// ---------------- fp16 tensor-core GEMM: C[M,N] = A[M,K] @ W[N,K]^T + bias ----------------
// ACT: 0 none, 1 relu, 2 tanh. CTA tile 128(M) x 64(N); K in chunks of 64.
// Requires M%128==0, N%64==0, K%64==0. 256 threads = 8 warps x 16 rows.
template<int ACT>
__global__ __launch_bounds__(256) void hgemm_kernel(const float* __restrict__ A,
                                                    const float* __restrict__ W,
                                                    const float* __restrict__ bias,
                                                    float* __restrict__ C,
                                                    int M, int N, int K) {
    __shared__ __half As[128][72];
    __shared__ __half Bs[64][72];
    int tid = threadIdx.x;
    int w = tid >> 5, lane = tid & 31;
    int bm = blockIdx.y * 128;
    int bn = blockIdx.x * 64;

    float acc[8][4];
    #pragma unroll
    for (int j = 0; j < 8; j++)
        #pragma unroll
        for (int c = 0; c < 4; c++) acc[j][c] = 0.f;

    for (int kt = 0; kt < K; kt += 64) {
        // ---- load + convert A tile: 128x64 fp32 -> fp16 (2048 float4, 8/thread) ----
        #pragma unroll
        for (int i = 0; i < 8; i++) {
            int idx = tid + i * 256;
            int row = idx >> 4;            // 16 float4 per row
            int c4  = (idx & 15) * 4;
            float4 f = *(const float4*)&A[(size_t)(bm + row) * K + kt + c4];
            __half2* d = (__half2*)&As[row][c4];
            d[0] = __floats2half2_rn(f.x, f.y);
            d[1] = __floats2half2_rn(f.z, f.w);
        }
        // ---- load + convert W tile: 64x64 (1024 float4, 4/thread) ----
        #pragma unroll
        for (int i = 0; i < 4; i++) {
            int idx = tid + i * 256;
            int row = idx >> 4;
            int c4  = (idx & 15) * 4;
            float4 f = *(const float4*)&W[(size_t)(bn + row) * K + kt + c4];
            __half2* d = (__half2*)&Bs[row][c4];
            d[0] = __floats2half2_rn(f.x, f.y);
            d[1] = __floats2half2_rn(f.z, f.w);
        }
        __syncthreads();

        #pragma unroll
        for (int ks2 = 0; ks2 < 2; ks2++) {   // two k=32 sub-chunks
            uint32_t af[2][4];
            #pragma unroll
            for (int s = 0; s < 2; s++) {
                int row = 16 * w + (lane & 15);
                int col = ks2 * 32 + s * 16 + (lane >> 4) * 8;
                LDSM4(af[s][0], af[s][1], af[s][2], af[s][3], smem_u32(&As[row][col]));
            }
            #pragma unroll
            for (int j = 0; j < 8; j++) {
                uint32_t bf[4];
                uint32_t addr = smem_u32(&Bs[8 * j + (lane & 7)][ks2 * 32 + (lane >> 3) * 8]);
                LDSM4(bf[0], bf[1], bf[2], bf[3], addr);
                MMA16816(acc[j], af[0][0], af[0][1], af[0][2], af[0][3], bf[0], bf[1]);
                MMA16816(acc[j], af[1][0], af[1][1], af[1][2], af[1][3], bf[2], bf[3]);
            }
        }
        __syncthreads();
    }

    // ---- epilogue: bias + activation, fp32 out ----
    int row0 = bm + 16 * w + (lane >> 2);
    int row1 = row0 + 8;
    #pragma unroll
    for (int j = 0; j < 8; j++) {
        int col = bn + 8 * j + 2 * (lane & 3);
        float b0 = bias[col], b1 = bias[col + 1];
        float v0 = acc[j][0] + b0, v1 = acc[j][1] + b1;
        float v2 = acc[j][2] + b0, v3 = acc[j][3] + b1;
        if (ACT == 1) { v0 = fmaxf(v0, 0.f); v1 = fmaxf(v1, 0.f); v2 = fmaxf(v2, 0.f); v3 = fmaxf(v3, 0.f); }
        if (ACT == 2) { v0 = tanhf(v0); v1 = tanhf(v1); v2 = tanhf(v2); v3 = tanhf(v3); }
        *(float2*)&C[(size_t)row0 * N + col] = make_float2(v0, v1);
        *(float2*)&C[(size_t)row1 * N + col] = make_float2(v2, v3);
    }
}

// ---------------- fp16 tensor-core flash attention ----------------
// QKV layout: [B, L, 384] q=[0,128) k=[128,256) v=[256,384); head h -> [h*32,(h+1)*32)
__global__ __launch_bounds__(256) void attn_mma_kernel(const float* __restrict__ QKV,
                                                       float* __restrict__ CTX) {
    int h = blockIdx.y;
    int b = blockIdx.z;
    int qbase = blockIdx.x * 128;
    int t = threadIdx.x;
    int w = t >> 5, lane = t & 31;

    __shared__ __half Qs[128][40];
    __shared__ __half Ks[64][40];
    __shared__ __half Vs[64][40];

    const float* base = QKV + (size_t)b * (LL * 384);

    // ---- load Q tile (scaled), fp32 -> fp16 ----
    {
        int row = t >> 1, c0 = (t & 1) * 16;
        const float4* src = (const float4*)(base + (size_t)(qbase + row) * 384 + h * 32 + c0);
        __half2* dst = (__half2*)&Qs[row][c0];
        #pragma unroll
        for (int i = 0; i < 4; i++) {
            float4 f = src[i];
            dst[2 * i]     = __floats2half2_rn(f.x * ATTN_SCALE, f.y * ATTN_SCALE);
            dst[2 * i + 1] = __floats2half2_rn(f.z * ATTN_SCALE, f.w * ATTN_SCALE);
        }
    }
    __syncthreads();

    // ---- Q fragments ----
    uint32_t qa[2][4];
    {
        int qr = w * 16;
        #pragma unroll
        for (int s = 0; s < 2; s++) {
            int row = qr + (lane & 15);
            int col = s * 16 + (lane >> 4) * 8;
            LDSM4(qa[s][0], qa[s][1], qa[s][2], qa[s][3], smem_u32(&Qs[row][col]));
        }
    }

    float oacc[4][4];
    #pragma unroll
    for (int j = 0; j < 4; j++)
        #pragma unroll
        for (int c = 0; c < 4; c++) oacc[j][c] = 0.f;
    float mrun0 = -1e30f, mrun1 = -1e30f, l0 = 0.f, l1 = 0.f;

    for (int kt = 0; kt < 16; kt++) {
        {
            int tt = t & 127;
            int row = tt >> 1, c0 = (tt & 1) * 16;
            int off = (t < 128) ? 128 : 256;
            const float4* src = (const float4*)(base + (size_t)(kt * 64 + row) * 384 + off + h * 32 + c0);
            __half2* dst = (t < 128) ? (__half2*)&Ks[row][c0] : (__half2*)&Vs[row][c0];
            #pragma unroll
            for (int i = 0; i < 4; i++) {
                float4 f = src[i];
                dst[2 * i]     = __floats2half2_rn(f.x, f.y);
                dst[2 * i + 1] = __floats2half2_rn(f.z, f.w);
            }
        }
        __syncthreads();

        float sacc[8][4];
        #pragma unroll
        for (int j = 0; j < 8; j++)
            #pragma unroll
            for (int c = 0; c < 4; c++) sacc[j][c] = 0.f;

        #pragma unroll
        for (int j = 0; j < 8; j++) {
            uint32_t kb[4];
            uint32_t addr = smem_u32(&Ks[8 * j + (lane & 7)][(lane >> 3) * 8]);
            LDSM4(kb[0], kb[1], kb[2], kb[3], addr);
            MMA16816(sacc[j], qa[0][0], qa[0][1], qa[0][2], qa[0][3], kb[0], kb[1]);
            MMA16816(sacc[j], qa[1][0], qa[1][1], qa[1][2], qa[1][3], kb[2], kb[3]);
        }

        float mx0 = -1e30f, mx1 = -1e30f;
        #pragma unroll
        for (int j = 0; j < 8; j++) {
            mx0 = fmaxf(mx0, fmaxf(sacc[j][0], sacc[j][1]));
            mx1 = fmaxf(mx1, fmaxf(sacc[j][2], sacc[j][3]));
        }
        #pragma unroll
        for (int o = 1; o <= 2; o <<= 1) {
            mx0 = fmaxf(mx0, __shfl_xor_sync(0xffffffffu, mx0, o));
            mx1 = fmaxf(mx1, __shfl_xor_sync(0xffffffffu, mx1, o));
        }
        float nm0 = fmaxf(mrun0, mx0), nm1 = fmaxf(mrun1, mx1);
        float al0 = __expf(mrun0 - nm0), al1 = __expf(mrun1 - nm1);
        mrun0 = nm0; mrun1 = nm1;

        float rs0 = 0.f, rs1 = 0.f;
        #pragma unroll
        for (int j = 0; j < 8; j++) {
            sacc[j][0] = __expf(sacc[j][0] - nm0); rs0 += sacc[j][0];
            sacc[j][1] = __expf(sacc[j][1] - nm0); rs0 += sacc[j][1];
            sacc[j][2] = __expf(sacc[j][2] - nm1); rs1 += sacc[j][2];
            sacc[j][3] = __expf(sacc[j][3] - nm1); rs1 += sacc[j][3];
        }
        #pragma unroll
        for (int o = 1; o <= 2; o <<= 1) {
            rs0 += __shfl_xor_sync(0xffffffffu, rs0, o);
            rs1 += __shfl_xor_sync(0xffffffffu, rs1, o);
        }
        l0 = l0 * al0 + rs0;
        l1 = l1 * al1 + rs1;
        #pragma unroll
        for (int j = 0; j < 4; j++) {
            oacc[j][0] *= al0; oacc[j][1] *= al0;
            oacc[j][2] *= al1; oacc[j][3] *= al1;
        }

        #pragma unroll
        for (int s = 0; s < 4; s++) {
            uint32_t pa0 = f2h2(sacc[2 * s][0], sacc[2 * s][1]);
            uint32_t pa1 = f2h2(sacc[2 * s][2], sacc[2 * s][3]);
            uint32_t pa2 = f2h2(sacc[2 * s + 1][0], sacc[2 * s + 1][1]);
            uint32_t pa3 = f2h2(sacc[2 * s + 1][2], sacc[2 * s + 1][3]);
            #pragma unroll
            for (int jj = 0; jj < 2; jj++) {
                uint32_t vb[4];
                uint32_t addr = smem_u32(&Vs[16 * s + (lane & 15)][8 * (2 * jj + (lane >> 4))]);
                LDSM4T(vb[0], vb[1], vb[2], vb[3], addr);
                MMA16816(oacc[2 * jj],     pa0, pa1, pa2, pa3, vb[0], vb[1]);
                MMA16816(oacc[2 * jj + 1], pa0, pa1, pa2, pa3, vb[2], vb[3]);
            }
        }
        __syncthreads();
    }

    float inv0 = 1.f / l0, inv1 = 1.f / l1;
    int r0 = qbase + w * 16 + (lane >> 2);
    float* o0 = CTX + ((size_t)(b * LL + r0)) * DIMD + h * 32 + 2 * (lane & 3);
    float* o1 = o0 + 8 * DIMD;
    #pragma unroll
    for (int j = 0; j < 4; j++) {
        *(float2*)(o0 + 8 * j) = make_float2(oacc[j][0] * inv0, oacc[j][1] * inv0);
        *(float2*)(o1 + 8 * j) = make_float2(oacc[j][2] * inv1, oacc[j][3] * inv1);
    }
}

// ---------------- residual + layernorm over DIM=128 ----------------
__global__ void ln_kernel(const float* __restrict__ x, const float* __restrict__ res,
                          const float* __restrict__ g, const float* __restrict__ b,
                          float* __restrict__ out) {
    int r = blockIdx.x;
    int t = threadIdx.x; // 128
    size_t idx = (size_t)r * DIMD + t;
    float v = x[idx] + res[idx];
    __shared__ float red[8];
    float s1 = warp_sum(v);
    float s2 = warp_sum(v * v);
    if ((t & 31) == 0) { red[t >> 5] = s1; red[4 + (t >> 5)] = s2; }
    __syncthreads();
    float sum   = red[0] + red[1] + red[2] + red[3];
    float sumsq = red[4] + red[5] + red[6] + red[7];
    float mean = sum * (1.0f / 128.0f);
    float var  = sumsq * (1.0f / 128.0f) - mean * mean;
    out[idx] = (v - mean) * rsqrtf(var + 1e-5f) * g[t] + b[t];
}

// ---------------- small-N GEMM: C[M,8] = A[M,128] @ W[8,128]^T + bias ----------------
__global__ __launch_bounds__(256) void gemm_n8(const float* __restrict__ A,
                                               const float* __restrict__ W,
                                               const float* __restrict__ bias,
                                               float* __restrict__ C) {
    __shared__ float As[32][128];
    __shared__ float Ws[8][128];
    int tid = threadIdx.x;
    size_t row0 = (size_t)blockIdx.x * 32;
    ((float4*)Ws)[tid] = ((const float4*)W)[tid];
    const float4* A4 = (const float4*)(A + row0 * 128);
    #pragma unroll
    for (int s = 0; s < 4; s++) ((float4*)As)[tid + s * 256] = A4[tid + s * 256];
    __syncthreads();
    int r = tid >> 3, j = tid & 7;
    float acc = 0.f;
    #pragma unroll
    for (int k4 = 0; k4 < 32; k4++) {
        float4 a = ((const float4*)As[r])[k4];
        float4 w = ((const float4*)Ws[j])[k4];
        acc += a.x * w.x + a.y * w.y + a.z * w.z + a.w * w.w;
    }
    C[(row0 + r) * MODEN + j] = acc + bias[j];
}

// ---------------- per-(b, mode) max-abs over N nodes ----------------
__global__ void maxabs_kernel(const float* __restrict__ phi, float* __restrict__ gmax) {
    int b = blockIdx.x;
    int n = threadIdx.x; // 256
    __shared__ float sm[256][8];
    #pragma unroll
    for (int j = 0; j < 8; j++)
        sm[n][j] = fabsf(phi[((size_t)b * NN + n) * MODEN + j]);
    __syncthreads();
    for (int s = 128; s > 0; s >>= 1) {
        if (n < s) {
            #pragma unroll
            for (int j = 0; j < 8; j++) sm[n][j] = fmaxf(sm[n][j], sm[n + s][j]);
        }
        __syncthreads();
    }
    if (n < 8) gmax[b * 8 + n] = sm[0][n];
}

__global__ void phinorm_kernel(const float* __restrict__ phi, const float* __restrict__ gmax,
                               float* __restrict__ out) {
    int i = blockIdx.x * 256 + threadIdx.x; // MP*MODEN = 65536
    int b = i >> 11;
    int j = i & 7;
    out[i] = phi[i] / gmax[b * 8 + j];
}

// ---------------- launch ----------------
extern "C" void kernel_launch(void* const* d_in, const int* in_sizes, int n_in,
                              void* d_out, int out_size) {
    (void)in_sizes; (void)n_in; (void)out_size;
    const float* acc_Y      = (const float*)d_in[0];
    const float* proj_in_w  = (const float*)d_in[2];
    const float* proj_in_b  = (const float*)d_in[3];
    const float* attn_in_w  = (const float*)d_in[4];
    const float* attn_in_b  = (const float*)d_in[5];
    const float* attn_out_w = (const float*)d_in[6];
    const float* attn_out_b = (const float*)d_in[7];
    const float* ln1_g      = (const float*)d_in[8];
    const float* ln1_b      = (const float*)d_in[9];
    const float* ff1_w      = (const float*)d_in[10];
    const float* ff1_b      = (const float*)d_in[11];
    const float* ff2_w      = (const float*)d_in[12];
    const float* ff2_b      = (const float*)d_in[13];
    const float* ln2_g      = (const float*)d_in[14];
    const float* ln2_b      = (const float*)d_in[15];
    const float* proj_out_w = (const float*)d_in[16];
    const float* proj_out_b = (const float*)d_in[17];
    const float* mlp1_w     = (const float*)d_in[18];
    const float* mlp1_b     = (const float*)d_in[19];
    const float* mlp2_w     = (const float*)d_in[20];
    const float* mlp2_b     = (const float*)d_in[21];
    const float* mlp3_w     = (const float*)d_in[22];
    const float* mlp3_b     = (const float*)d_in[23];
    float* out = (float*)d_out;

    float *pX, *pX2, *pQKV, *pCTX, *pTMP, *pH1, *pH2, *pPHI, *pMAX;
    cudaGetSymbolAddress((void**)&pX,   g_X);
    cudaGetSymbolAddress((void**)&pX2,  g_X2);
    cudaGetSymbolAddress((void**)&pQKV, g_QKV);
    cudaGetSymbolAddress((void**)&pCTX, g_CTX);
    cudaGetSymbolAddress((void**)&pTMP, g_TMP);
    cudaGetSymbolAddress((void**)&pH1,  g_H1);
    cudaGetSymbolAddress((void**)&pH2,  g_H2);
    cudaGetSymbolAddress((void**)&pPHI, g_PHI);
    cudaGetSymbolAddress((void**)&pMAX, g_MAX);

    // ===== q path =====
    proj_in_kernel<<<MQ, 128>>>(acc_Y, proj_in_w, proj_in_b, pX);
    hgemm_kernel<0><<<dim3(6, MQ / 128), 256>>>(pX, attn_in_w, attn_in_b, pQKV, MQ, 384, 128);
    attn_mma_kernel<<<dim3(LL / 128, HH, BB), 256>>>(pQKV, pCTX);
    hgemm_kernel<0><<<dim3(2, MQ / 128), 256>>>(pCTX, attn_out_w, attn_out_b, pTMP, MQ, 128, 128);
    ln_kernel<<<MQ, 128>>>(pX, pTMP, ln1_g, ln1_b, pX2);
    hgemm_kernel<1><<<dim3(4, MQ / 128), 256>>>(pX2, ff1_w, ff1_b, pTMP, MQ, 256, 128);
    hgemm_kernel<0><<<dim3(2, MQ / 128), 256>>>(pTMP, ff2_w, ff2_b, pCTX, MQ, 128, 256);
    ln_kernel<<<MQ, 128>>>(pX2, pCTX, ln2_g, ln2_b, pX);
    gemm_n8<<<MQ / 32, 256>>>(pX, proj_out_w, proj_out_b, out);   // q -> out[0 : 262144)

    // ===== phi path =====
    hgemm_kernel<2><<<dim3(2, MP / 128), 256>>>(acc_Y, mlp1_w, mlp1_b, pH1, MP, 128, 1024);
    hgemm_kernel<2><<<dim3(2, MP / 128), 256>>>(pH1, mlp2_w, mlp2_b, pH2, MP, 128, 128);
    hgemm_kernel<2><<<dim3(2, MP / 128), 256>>>(pH2, mlp2_w, mlp2_b, pH1, MP, 128, 128);
    gemm_n8<<<MP / 32, 256>>>(pH1, mlp3_w, mlp3_b, pPHI);
    maxabs_kernel<<<BB, 256>>>(pPHI, pMAX);
    phinorm_kernel<<<(MP * MODEN) / 256, 256>>>(pPHI, pMAX, out + MQ * MODEN);
}

// round 9
// speedup vs baseline: 3.2043x; 1.0283x over previous
#include <cuda_runtime.h>
#include <cuda_fp16.h>
#include <cuda_bf16.h>
#include <math.h>
#include <stdint.h>

// ---------------- problem constants ----------------
#define BB    32
#define NN    256
#define LL    1024
#define DIMD  128
#define MODEN 8
#define HH    4
#define DHD   32
#define FFD   256
#define MQ    (BB*LL)    // 32768 rows, q path
#define MP    (BB*NN)    // 8192 rows, phi path
#define ATTN_SCALE 0.17677669529663687f  // 1/sqrt(32)

// ---------------- scratch (device globals; no allocation allowed) ----------------
__device__ float  g_X   [MQ * DIMD];
__device__ float  g_X2  [MQ * DIMD];
__device__ float  g_TMP [MQ * DIMD];     // attn_out output (fp32, feeds LN)
__device__ float  g_FF2 [MQ * DIMD];     // ff2 output (fp32, feeds LN)
__device__ __half g_QKVh[MQ * 3 * DIMD];
__device__ __half g_CTXh[MQ * DIMD];
__device__ __half g_TMPh[MQ * FFD];
__device__ float  g_H1  [MP * DIMD];
__device__ float  g_H2  [MP * DIMD];
__device__ float  g_PHI [MP * MODEN];
__device__ float  g_MAX [BB * MODEN];

// ---------------- helpers ----------------
__inline__ __device__ float warp_sum(float v) {
    #pragma unroll
    for (int o = 16; o > 0; o >>= 1) v += __shfl_xor_sync(0xffffffffu, v, o);
    return v;
}

__device__ __forceinline__ uint32_t smem_u32(const void* p) {
    return (uint32_t)__cvta_generic_to_shared(p);
}

__device__ __forceinline__ uint32_t f2h2(float a, float b) {
    __half2 h = __floats2half2_rn(a, b);
    return *reinterpret_cast<uint32_t*>(&h);
}

#define LDSM4(r0,r1,r2,r3,addr) \
    asm volatile("ldmatrix.sync.aligned.m8n8.x4.shared.b16 {%0,%1,%2,%3},[%4];" \
                 : "=r"(r0),"=r"(r1),"=r"(r2),"=r"(r3) : "r"(addr))
#define LDSM4T(r0,r1,r2,r3,addr) \
    asm volatile("ldmatrix.sync.aligned.m8n8.x4.trans.shared.b16 {%0,%1,%2,%3},[%4];" \
                 : "=r"(r0),"=r"(r1),"=r"(r2),"=r"(r3) : "r"(addr))
#define MMA16816(c,a0,a1,a2,a3,b0,b1) \
    asm volatile("mma.sync.aligned.m16n8k16.row.col.f32.f16.f16.f32 " \
                 "{%0,%1,%2,%3},{%4,%5,%6,%7},{%8,%9},{%0,%1,%2,%3};" \
                 : "+f"(c[0]),"+f"(c[1]),"+f"(c[2]),"+f"(c[3]) \
                 : "r"(a0),"r"(a1),"r"(a2),"r"(a3),"r"(b0),"r"(b1))

// ---------------- proj_in ----------------
__global__ void proj_in_kernel(const float* __restrict__ Y,
                               const float* __restrict__ w,
                               const float* __restrict__ bias,
                               float* __restrict__ X) {
    int r = blockIdx.x;
    int b = r >> 10;
    int l = r & 1023;
    int t = threadIdx.x;              // 128
    __shared__ float xs[7];
    if (t < 7) xs[t] = Y[((size_t)b * NN + 2 + t) * LL + l];
    __syncthreads();
    float acc = bias[t];
    #pragma unroll
    for (int j = 0; j < 7; j++) acc += xs[j] * w[t * 7 + j];
    X[(size_t)r * DIMD + t] = acc;
}

// ---------------- fp16 tensor-core GEMM ----------------
// C[M,N] = A[M,K] @ W[N,K]^T + bias. ACT: 0 none, 1 relu, 2 tanh.
// AHALF: A is __half (else fp32, converted on load). CHALF: C written as __half.
// CTA tile 128(M) x 64(N); K chunks of 64. M%128==0, N%64==0, K%64==0.
template<int ACT, int AHALF, int CHALF>
__global__ __launch_bounds__(256) void hgemm_kernel(const void* __restrict__ Av,
                                                    const float* __restrict__ W,
                                                    const float* __restrict__ bias,
                                                    void* __restrict__ Cv,
                                                    int M, int N, int K) {
    __shared__ __half As[128][72];
    __shared__ __half Bs[64][72];
    int tid = threadIdx.x;
    int w = tid >> 5, lane = tid & 31;
    int bm = blockIdx.y * 128;
    int bn = blockIdx.x * 64;

    float acc[8][4];
    #pragma unroll
    for (int j = 0; j < 8; j++)
        #pragma unroll
        for (int c = 0; c < 4; c++) acc[j][c] = 0.f;

    for (int kt = 0; kt < K; kt += 64) {
        if (AHALF) {
            const __half* A = (const __half*)Av;
            #pragma unroll
            for (int i = 0; i < 4; i++) {
                int idx = tid + i * 256;
                int row = idx >> 3;          // 8 uint4 per row (64 halves)
                int c8  = (idx & 7) * 8;
                *(uint4*)&As[row][c8] =
                    *(const uint4*)&A[(size_t)(bm + row) * K + kt + c8];
            }
        } else {
            const float* A = (const float*)Av;
            #pragma unroll
            for (int i = 0; i < 8; i++) {
                int idx = tid + i * 256;
                int row = idx >> 4;          // 16 float4 per row
                int c4  = (idx & 15) * 4;
                float4 f = *(const float4*)&A[(size_t)(bm + row) * K + kt + c4];
                __half2* d = (__half2*)&As[row][c4];
                d[0] = __floats2half2_rn(f.x, f.y);
                d[1] = __floats2half2_rn(f.z, f.w);
            }
        }
        #pragma unroll
        for (int i = 0; i < 4; i++) {
            int idx = tid + i * 256;
            int row = idx >> 4;
            int c4  = (idx & 15) * 4;
            float4 f = *(const float4*)&W[(size_t)(bn + row) * K + kt + c4];
            __half2* d = (__half2*)&Bs[row][c4];
            d[0] = __floats2half2_rn(f.x, f.y);
            d[1] = __floats2half2_rn(f.z, f.w);
        }
        __syncthreads();

        #pragma unroll
        for (int ks2 = 0; ks2 < 2; ks2++) {
            uint32_t af[2][4];
            #pragma unroll
            for (int s = 0; s < 2; s++) {
                int row = 16 * w + (lane & 15);
                int col = ks2 * 32 + s * 16 + (lane >> 4) * 8;
                LDSM4(af[s][0], af[s][1], af[s][2], af[s][3], smem_u32(&As[row][col]));
            }
            #pragma unroll
            for (int j = 0; j < 8; j++) {
                uint32_t bf[4];
                uint32_t addr = smem_u32(&Bs[8 * j + (lane & 7)][ks2 * 32 + (lane >> 3) * 8]);
                LDSM4(bf[0], bf[1], bf[2], bf[3], addr);
                MMA16816(acc[j], af[0][0], af[0][1], af[0][2], af[0][3], bf[0], bf[1]);
                MMA16816(acc[j], af[1][0], af[1][1], af[1][2], af[1][3], bf[2], bf[3]);
            }
        }
        __syncthreads();
    }

    int row0 = bm + 16 * w + (lane >> 2);
    int row1 = row0 + 8;
    #pragma unroll
    for (int j = 0; j < 8; j++) {
        int col = bn + 8 * j + 2 * (lane & 3);
        float b0 = bias[col], b1 = bias[col + 1];
        float v0 = acc[j][0] + b0, v1 = acc[j][1] + b1;
        float v2 = acc[j][2] + b0, v3 = acc[j][3] + b1;
        if (ACT == 1) { v0 = fmaxf(v0, 0.f); v1 = fmaxf(v1, 0.f); v2 = fmaxf(v2, 0.f); v3 = fmaxf(v3, 0.f); }
        if (ACT == 2) { v0 = tanhf(v0); v1 = tanhf(v1); v2 = tanhf(v2); v3 = tanhf(v3); }
        if (CHALF) {
            __half* C = (__half*)Cv;
            *(__half2*)&C[(size_t)row0 * N + col] = __floats2half2_rn(v0, v1);
            *(__half2*)&C[(size_t)row1 * N + col] = __floats2half2_rn(v2, v3);
        } else {
            float* C = (float*)Cv;
            *(float2*)&C[(size_t)row0 * N + col] = make_float2(v0, v1);
            *(float2*)&C[(size_t)row1 * N + col] = make_float2(v2, v3);
        }
    }
}

// ---------------- fp16 tensor-core flash attention (fp16 in/out, prefetch) ----------------
// QKVh layout: [B, L, 384] halves, q=[0,128) k=[128,256) v=[256,384); head h -> [h*32,(h+1)*32)
__global__ __launch_bounds__(256) void attn_mma_kernel(const __half* __restrict__ QKV,
                                                       __half* __restrict__ CTX) {
    int h = blockIdx.y;
    int b = blockIdx.z;
    int qbase = blockIdx.x * 128;
    int t = threadIdx.x;
    int w = t >> 5, lane = t & 31;

    __shared__ __half Qs[128][40];
    __shared__ __half Ks[64][40];
    __shared__ __half Vs[64][40];

    const __half* base = QKV + (size_t)b * (LL * 384);

    // ---- load Q tile (half, direct copy): 512 uint4, 2/thread ----
    #pragma unroll
    for (int i = 0; i < 2; i++) {
        int idx = t + i * 256;
        int row = idx >> 2;
        int c8  = (idx & 3) * 8;
        *(uint4*)&Qs[row][c8] =
            *(const uint4*)(base + (size_t)(qbase + row) * 384 + h * 32 + c8);
    }

    // ---- prefetch K/V tile 0 into registers ----
    int tt = t & 127;
    int krow = tt >> 1;
    int kc0  = (tt & 1) * 16;
    int koff = (t < 128) ? 128 : 256;
    uint4 pf0, pf1;
    {
        const uint4* s = (const uint4*)(base + (size_t)(0 * 64 + krow) * 384 + koff + h * 32 + kc0);
        pf0 = s[0]; pf1 = s[1];
    }
    __syncthreads();

    // ---- Q fragments ----
    uint32_t qa[2][4];
    {
        int qr = w * 16;
        #pragma unroll
        for (int s = 0; s < 2; s++) {
            int row = qr + (lane & 15);
            int col = s * 16 + (lane >> 4) * 8;
            LDSM4(qa[s][0], qa[s][1], qa[s][2], qa[s][3], smem_u32(&Qs[row][col]));
        }
    }

    float oacc[4][4];
    #pragma unroll
    for (int j = 0; j < 4; j++)
        #pragma unroll
        for (int c = 0; c < 4; c++) oacc[j][c] = 0.f;
    float mrun0 = -1e30f, mrun1 = -1e30f, l0 = 0.f, l1 = 0.f;

    for (int kt = 0; kt < 16; kt++) {
        // ---- commit prefetched tile to smem ----
        {
            uint4* d = (uint4*)&((t < 128) ? Ks : Vs)[krow][kc0];
            d[0] = pf0; d[1] = pf1;
        }
        __syncthreads();
        // ---- prefetch next tile (overlaps with compute below) ----
        if (kt < 15) {
            const uint4* s = (const uint4*)(base + (size_t)((kt + 1) * 64 + krow) * 384 + koff + h * 32 + kc0);
            pf0 = s[0]; pf1 = s[1];
        }

        // ---- S = Q K^T ----
        float sacc[8][4];
        #pragma unroll
        for (int j = 0; j < 8; j++)
            #pragma unroll
            for (int c = 0; c < 4; c++) sacc[j][c] = 0.f;

        #pragma unroll
        for (int j = 0; j < 8; j++) {
            uint32_t kb[4];
            uint32_t addr = smem_u32(&Ks[8 * j + (lane & 7)][(lane >> 3) * 8]);
            LDSM4(kb[0], kb[1], kb[2], kb[3], addr);
            MMA16816(sacc[j], qa[0][0], qa[0][1], qa[0][2], qa[0][3], kb[0], kb[1]);
            MMA16816(sacc[j], qa[1][0], qa[1][1], qa[1][2], qa[1][3], kb[2], kb[3]);
        }
        // exact fp32 softmax scale
        #pragma unroll
        for (int j = 0; j < 8; j++)
            #pragma unroll
            for (int c = 0; c < 4; c++) sacc[j][c] *= ATTN_SCALE;

        // ---- online softmax ----
        float mx0 = -1e30f, mx1 = -1e30f;
        #pragma unroll
        for (int j = 0; j < 8; j++) {
            mx0 = fmaxf(mx0, fmaxf(sacc[j][0], sacc[j][1]));
            mx1 = fmaxf(mx1, fmaxf(sacc[j][2], sacc[j][3]));
        }
        #pragma unroll
        for (int o = 1; o <= 2; o <<= 1) {
            mx0 = fmaxf(mx0, __shfl_xor_sync(0xffffffffu, mx0, o));
            mx1 = fmaxf(mx1, __shfl_xor_sync(0xffffffffu, mx1, o));
        }
        float nm0 = fmaxf(mrun0, mx0), nm1 = fmaxf(mrun1, mx1);
        float al0 = __expf(mrun0 - nm0), al1 = __expf(mrun1 - nm1);
        mrun0 = nm0; mrun1 = nm1;

        float rs0 = 0.f, rs1 = 0.f;
        #pragma unroll
        for (int j = 0; j < 8; j++) {
            sacc[j][0] = __expf(sacc[j][0] - nm0); rs0 += sacc[j][0];
            sacc[j][1] = __expf(sacc[j][1] - nm0); rs0 += sacc[j][1];
            sacc[j][2] = __expf(sacc[j][2] - nm1); rs1 += sacc[j][2];
            sacc[j][3] = __expf(sacc[j][3] - nm1); rs1 += sacc[j][3];
        }
        #pragma unroll
        for (int o = 1; o <= 2; o <<= 1) {
            rs0 += __shfl_xor_sync(0xffffffffu, rs0, o);
            rs1 += __shfl_xor_sync(0xffffffffu, rs1, o);
        }
        l0 = l0 * al0 + rs0;
        l1 = l1 * al1 + rs1;
        #pragma unroll
        for (int j = 0; j < 4; j++) {
            oacc[j][0] *= al0; oacc[j][1] *= al0;
            oacc[j][2] *= al1; oacc[j][3] *= al1;
        }

        // ---- O += P V ----
        #pragma unroll
        for (int s = 0; s < 4; s++) {
            uint32_t pa0 = f2h2(sacc[2 * s][0], sacc[2 * s][1]);
            uint32_t pa1 = f2h2(sacc[2 * s][2], sacc[2 * s][3]);
            uint32_t pa2 = f2h2(sacc[2 * s + 1][0], sacc[2 * s + 1][1]);
            uint32_t pa3 = f2h2(sacc[2 * s + 1][2], sacc[2 * s + 1][3]);
            #pragma unroll
            for (int jj = 0; jj < 2; jj++) {
                uint32_t vb[4];
                uint32_t addr = smem_u32(&Vs[16 * s + (lane & 15)][8 * (2 * jj + (lane >> 4))]);
                LDSM4T(vb[0], vb[1], vb[2], vb[3], addr);
                MMA16816(oacc[2 * jj],     pa0, pa1, pa2, pa3, vb[0], vb[1]);
                MMA16816(oacc[2 * jj + 1], pa0, pa1, pa2, pa3, vb[2], vb[3]);
            }
        }
        __syncthreads();
    }

    // ---- epilogue (half out) ----
    float inv0 = 1.f / l0, inv1 = 1.f / l1;
    int r0 = qbase + w * 16 + (lane >> 2);
    __half* o0 = CTX + ((size_t)(b * LL + r0)) * DIMD + h * 32 + 2 * (lane & 3);
    __half* o1 = o0 + 8 * DIMD;
    #pragma unroll
    for (int j = 0; j < 4; j++) {
        *(__half2*)(o0 + 8 * j) = __floats2half2_rn(oacc[j][0] * inv0, oacc[j][1] * inv0);
        *(__half2*)(o1 + 8 * j) = __floats2half2_rn(oacc[j][2] * inv1, oacc[j][3] * inv1);
    }
}

// ---------------- residual + layernorm over DIM=128 ----------------
__global__ void ln_kernel(const float* __restrict__ x, const float* __restrict__ res,
                          const float* __restrict__ g, const float* __restrict__ b,
                          float* __restrict__ out) {
    int r = blockIdx.x;
    int t = threadIdx.x; // 128
    size_t idx = (size_t)r * DIMD + t;
    float v = x[idx] + res[idx];
    __shared__ float red[8];
    float s1 = warp_sum(v);
    float s2 = warp_sum(v * v);
    if ((t & 31) == 0) { red[t >> 5] = s1; red[4 + (t >> 5)] = s2; }
    __syncthreads();
    float sum   = red[0] + red[1] + red[2] + red[3];
    float sumsq = red[4] + red[5] + red[6] + red[7];
    float mean = sum * (1.0f / 128.0f);
    float var  = sumsq * (1.0f / 128.0f) - mean * mean;
    out[idx] = (v - mean) * rsqrtf(var + 1e-5f) * g[t] + b[t];
}

// ---------------- small-N GEMM: C[M,8] = A[M,128] @ W[8,128]^T + bias ----------------
__global__ __launch_bounds__(256) void gemm_n8(const float* __restrict__ A,
                                               const float* __restrict__ W,
                                               const float* __restrict__ bias,
                                               float* __restrict__ C) {
    __shared__ float As[32][128];
    __shared__ float Ws[8][128];
    int tid = threadIdx.x;
    size_t row0 = (size_t)blockIdx.x * 32;
    ((float4*)Ws)[tid] = ((const float4*)W)[tid];
    const float4* A4 = (const float4*)(A + row0 * 128);
    #pragma unroll
    for (int s = 0; s < 4; s++) ((float4*)As)[tid + s * 256] = A4[tid + s * 256];
    __syncthreads();
    int r = tid >> 3, j = tid & 7;
    float acc = 0.f;
    #pragma unroll
    for (int k4 = 0; k4 < 32; k4++) {
        float4 a = ((const float4*)As[r])[k4];
        float4 w = ((const float4*)Ws[j])[k4];
        acc += a.x * w.x + a.y * w.y + a.z * w.z + a.w * w.w;
    }
    C[(row0 + r) * MODEN + j] = acc + bias[j];
}

// ---------------- per-(b, mode) max-abs over N nodes ----------------
__global__ void maxabs_kernel(const float* __restrict__ phi, float* __restrict__ gmax) {
    int b = blockIdx.x;
    int n = threadIdx.x; // 256
    __shared__ float sm[256][8];
    #pragma unroll
    for (int j = 0; j < 8; j++)
        sm[n][j] = fabsf(phi[((size_t)b * NN + n) * MODEN + j]);
    __syncthreads();
    for (int s = 128; s > 0; s >>= 1) {
        if (n < s) {
            #pragma unroll
            for (int j = 0; j < 8; j++) sm[n][j] = fmaxf(sm[n][j], sm[n + s][j]);
        }
        __syncthreads();
    }
    if (n < 8) gmax[b * 8 + n] = sm[0][n];
}

__global__ void phinorm_kernel(const float* __restrict__ phi, const float* __restrict__ gmax,
                               float* __restrict__ out) {
    int i = blockIdx.x * 256 + threadIdx.x; // MP*MODEN = 65536
    int b = i >> 11;
    int j = i & 7;
    out[i] = phi[i] / gmax[b * 8 + j];
}

// ---------------- launch ----------------
extern "C" void kernel_launch(void* const* d_in, const int* in_sizes, int n_in,
                              void* d_out, int out_size) {
    (void)in_sizes; (void)n_in; (void)out_size;
    const float* acc_Y      = (const float*)d_in[0];
    const float* proj_in_w  = (const float*)d_in[2];
    const float* proj_in_b  = (const float*)d_in[3];
    const float* attn_in_w  = (const float*)d_in[4];
    const float* attn_in_b  = (const float*)d_in[5];
    const float* attn_out_w = (const float*)d_in[6];
    const float* attn_out_b = (const float*)d_in[7];
    const float* ln1_g      = (const float*)d_in[8];
    const float* ln1_b      = (const float*)d_in[9];
    const float* ff1_w      = (const float*)d_in[10];
    const float* ff1_b      = (const float*)d_in[11];
    const float* ff2_w      = (const float*)d_in[12];
    const float* ff2_b      = (const float*)d_in[13];
    const float* ln2_g      = (const float*)d_in[14];
    const float* ln2_b      = (const float*)d_in[15];
    const float* proj_out_w = (const float*)d_in[16];
    const float* proj_out_b = (const float*)d_in[17];
    const float* mlp1_w     = (const float*)d_in[18];
    const float* mlp1_b     = (const float*)d_in[19];
    const float* mlp2_w     = (const float*)d_in[20];
    const float* mlp2_b     = (const float*)d_in[21];
    const float* mlp3_w     = (const float*)d_in[22];
    const float* mlp3_b     = (const float*)d_in[23];
    float* out = (float*)d_out;

    float  *pX, *pX2, *pTMP, *pFF2, *pH1, *pH2, *pPHI, *pMAX;
    __half *pQKVh, *pCTXh, *pTMPh;
    cudaGetSymbolAddress((void**)&pX,    g_X);
    cudaGetSymbolAddress((void**)&pX2,   g_X2);
    cudaGetSymbolAddress((void**)&pTMP,  g_TMP);
    cudaGetSymbolAddress((void**)&pFF2,  g_FF2);
    cudaGetSymbolAddress((void**)&pQKVh, g_QKVh);
    cudaGetSymbolAddress((void**)&pCTXh, g_CTXh);
    cudaGetSymbolAddress((void**)&pTMPh, g_TMPh);
    cudaGetSymbolAddress((void**)&pH1,   g_H1);
    cudaGetSymbolAddress((void**)&pH2,   g_H2);
    cudaGetSymbolAddress((void**)&pPHI,  g_PHI);
    cudaGetSymbolAddress((void**)&pMAX,  g_MAX);

    // ===== q path =====
    proj_in_kernel<<<MQ, 128>>>(acc_Y, proj_in_w, proj_in_b, pX);
    hgemm_kernel<0,0,1><<<dim3(6, MQ / 128), 256>>>(pX, attn_in_w, attn_in_b, pQKVh, MQ, 384, 128);
    attn_mma_kernel<<<dim3(LL / 128, HH, BB), 256>>>(pQKVh, pCTXh);
    hgemm_kernel<0,1,0><<<dim3(2, MQ / 128), 256>>>(pCTXh, attn_out_w, attn_out_b, pTMP, MQ, 128, 128);
    ln_kernel<<<MQ, 128>>>(pX, pTMP, ln1_g, ln1_b, pX2);
    hgemm_kernel<1,0,1><<<dim3(4, MQ / 128), 256>>>(pX2, ff1_w, ff1_b, pTMPh, MQ, 256, 128);
    hgemm_kernel<0,1,0><<<dim3(2, MQ / 128), 256>>>(pTMPh, ff2_w, ff2_b, pFF2, MQ, 128, 256);
    ln_kernel<<<MQ, 128>>>(pX2, pFF2, ln2_g, ln2_b, pX);
    gemm_n8<<<MQ / 32, 256>>>(pX, proj_out_w, proj_out_b, out);   // q -> out[0 : 262144)

    // ===== phi path =====
    hgemm_kernel<2,0,0><<<dim3(2, MP / 128), 256>>>(acc_Y, mlp1_w, mlp1_b, pH1, MP, 128, 1024);
    hgemm_kernel<2,0,0><<<dim3(2, MP / 128), 256>>>(pH1, mlp2_w, mlp2_b, pH2, MP, 128, 128);
    hgemm_kernel<2,0,0><<<dim3(2, MP / 128), 256>>>(pH2, mlp2_w, mlp2_b, pH1, MP, 128, 128);
    gemm_n8<<<MP / 32, 256>>>(pH1, mlp3_w, mlp3_b, pPHI);
    maxabs_kernel<<<BB, 256>>>(pPHI, pMAX);
    phinorm_kernel<<<(MP * MODEN) / 256, 256>>>(pPHI, pMAX, out + MQ * MODEN);
}

// round 11
// speedup vs baseline: 4.0019x; 1.2489x over previous
#include <cuda_runtime.h>
#include <cuda_fp16.h>
#include <cuda_bf16.h>
#include <math.h>
#include <stdint.h>

// ---------------- problem constants ----------------
#define BB    32
#define NN    256
#define LL    1024
#define DIMD  128
#define MODEN 8
#define HH    4
#define DHD   32
#define FFD   256
#define MQ    (BB*LL)    // 32768 rows, q path
#define MP    (BB*NN)    // 8192 rows, phi path
#define ATTN_SCALE 0.17677669529663687f  // 1/sqrt(32)

// ---------------- scratch (device globals; no allocation allowed) ----------------
__device__ float  g_X   [MQ * DIMD];     // proj_in out (fp32, residual 1)
__device__ __half g_Xh  [MQ * DIMD];     // proj_in out (fp16, QKV gemm input)
__device__ float  g_X2  [MQ * DIMD];     // LN1 out (fp32, residual 2)
__device__ __half g_X2h [MQ * DIMD];     // LN1 out (fp16, ff1 input)
__device__ __half g_QKVh[MQ * 3 * DIMD];
__device__ __half g_CTXh[MQ * DIMD];
__device__ __half g_TMPh[MQ * FFD];      // ff1 out (fp16)
__device__ float  g_H1  [MP * DIMD];
__device__ float  g_H2  [MP * DIMD];
__device__ float  g_PHI [MP * MODEN];
__device__ float  g_MAX [BB * MODEN];

// ---------------- helpers ----------------
__inline__ __device__ float warp_sum(float v) {
    #pragma unroll
    for (int o = 16; o > 0; o >>= 1) v += __shfl_xor_sync(0xffffffffu, v, o);
    return v;
}

__device__ __forceinline__ uint32_t smem_u32(const void* p) {
    return (uint32_t)__cvta_generic_to_shared(p);
}

__device__ __forceinline__ uint32_t f2h2(float a, float b) {
    __half2 h = __floats2half2_rn(a, b);
    return *reinterpret_cast<uint32_t*>(&h);
}

#define LDSM4(r0,r1,r2,r3,addr) \
    asm volatile("ldmatrix.sync.aligned.m8n8.x4.shared.b16 {%0,%1,%2,%3},[%4];" \
                 : "=r"(r0),"=r"(r1),"=r"(r2),"=r"(r3) : "r"(addr))
#define LDSM4T(r0,r1,r2,r3,addr) \
    asm volatile("ldmatrix.sync.aligned.m8n8.x4.trans.shared.b16 {%0,%1,%2,%3},[%4];" \
                 : "=r"(r0),"=r"(r1),"=r"(r2),"=r"(r3) : "r"(addr))
#define MMA16816(c,a0,a1,a2,a3,b0,b1) \
    asm volatile("mma.sync.aligned.m16n8k16.row.col.f32.f16.f16.f32 " \
                 "{%0,%1,%2,%3},{%4,%5,%6,%7},{%8,%9},{%0,%1,%2,%3};" \
                 : "+f"(c[0]),"+f"(c[1]),"+f"(c[2]),"+f"(c[3]) \
                 : "r"(a0),"r"(a1),"r"(a2),"r"(a3),"r"(b0),"r"(b1))

// ---------------- proj_in: writes fp32 + fp16 ----------------
__global__ void proj_in_kernel(const float* __restrict__ Y,
                               const float* __restrict__ w,
                               const float* __restrict__ bias,
                               float* __restrict__ X,
                               __half* __restrict__ Xh) {
    int r = blockIdx.x;
    int b = r >> 10;
    int l = r & 1023;
    int t = threadIdx.x;              // 128
    __shared__ float xs[7];
    if (t < 7) xs[t] = Y[((size_t)b * NN + 2 + t) * LL + l];
    __syncthreads();
    float acc = bias[t];
    #pragma unroll
    for (int j = 0; j < 7; j++) acc += xs[j] * w[t * 7 + j];
    X[(size_t)r * DIMD + t]  = acc;
    Xh[(size_t)r * DIMD + t] = __float2half(acc);
}

// ---------------- fp16 tensor-core GEMM (N-tile 64) ----------------
// C[M,N] = A[M,K] @ W[N,K]^T + bias. ACT: 0 none, 1 relu, 2 tanh.
// AHALF: A is __half. CHALF: C written as __half.
template<int ACT, int AHALF, int CHALF>
__global__ __launch_bounds__(256) void hgemm_kernel(const void* __restrict__ Av,
                                                    const float* __restrict__ W,
                                                    const float* __restrict__ bias,
                                                    void* __restrict__ Cv,
                                                    int M, int N, int K) {
    __shared__ __half As[128][72];
    __shared__ __half Bs[64][72];
    int tid = threadIdx.x;
    int w = tid >> 5, lane = tid & 31;
    int bm = blockIdx.y * 128;
    int bn = blockIdx.x * 64;

    float acc[8][4];
    #pragma unroll
    for (int j = 0; j < 8; j++)
        #pragma unroll
        for (int c = 0; c < 4; c++) acc[j][c] = 0.f;

    for (int kt = 0; kt < K; kt += 64) {
        if (AHALF) {
            const __half* A = (const __half*)Av;
            #pragma unroll
            for (int i = 0; i < 4; i++) {
                int idx = tid + i * 256;
                int row = idx >> 3;
                int c8  = (idx & 7) * 8;
                *(uint4*)&As[row][c8] =
                    *(const uint4*)&A[(size_t)(bm + row) * K + kt + c8];
            }
        } else {
            const float* A = (const float*)Av;
            #pragma unroll
            for (int i = 0; i < 8; i++) {
                int idx = tid + i * 256;
                int row = idx >> 4;
                int c4  = (idx & 15) * 4;
                float4 f = *(const float4*)&A[(size_t)(bm + row) * K + kt + c4];
                __half2* d = (__half2*)&As[row][c4];
                d[0] = __floats2half2_rn(f.x, f.y);
                d[1] = __floats2half2_rn(f.z, f.w);
            }
        }
        #pragma unroll
        for (int i = 0; i < 4; i++) {
            int idx = tid + i * 256;
            int row = idx >> 4;
            int c4  = (idx & 15) * 4;
            float4 f = *(const float4*)&W[(size_t)(bn + row) * K + kt + c4];
            __half2* d = (__half2*)&Bs[row][c4];
            d[0] = __floats2half2_rn(f.x, f.y);
            d[1] = __floats2half2_rn(f.z, f.w);
        }
        __syncthreads();

        #pragma unroll
        for (int ks2 = 0; ks2 < 2; ks2++) {
            uint32_t af[2][4];
            #pragma unroll
            for (int s = 0; s < 2; s++) {
                int row = 16 * w + (lane & 15);
                int col = ks2 * 32 + s * 16 + (lane >> 4) * 8;
                LDSM4(af[s][0], af[s][1], af[s][2], af[s][3], smem_u32(&As[row][col]));
            }
            #pragma unroll
            for (int j = 0; j < 8; j++) {
                uint32_t bf[4];
                uint32_t addr = smem_u32(&Bs[8 * j + (lane & 7)][ks2 * 32 + (lane >> 3) * 8]);
                LDSM4(bf[0], bf[1], bf[2], bf[3], addr);
                MMA16816(acc[j], af[0][0], af[0][1], af[0][2], af[0][3], bf[0], bf[1]);
                MMA16816(acc[j], af[1][0], af[1][1], af[1][2], af[1][3], bf[2], bf[3]);
            }
        }
        __syncthreads();
    }

    int row0 = bm + 16 * w + (lane >> 2);
    int row1 = row0 + 8;
    #pragma unroll
    for (int j = 0; j < 8; j++) {
        int col = bn + 8 * j + 2 * (lane & 3);
        float b0 = bias[col], b1 = bias[col + 1];
        float v0 = acc[j][0] + b0, v1 = acc[j][1] + b1;
        float v2 = acc[j][2] + b0, v3 = acc[j][3] + b1;
        if (ACT == 1) { v0 = fmaxf(v0, 0.f); v1 = fmaxf(v1, 0.f); v2 = fmaxf(v2, 0.f); v3 = fmaxf(v3, 0.f); }
        if (ACT == 2) { v0 = tanhf(v0); v1 = tanhf(v1); v2 = tanhf(v2); v3 = tanhf(v3); }
        if (CHALF) {
            __half* C = (__half*)Cv;
            *(__half2*)&C[(size_t)row0 * N + col] = __floats2half2_rn(v0, v1);
            *(__half2*)&C[(size_t)row1 * N + col] = __floats2half2_rn(v2, v3);
        } else {
            float* C = (float*)Cv;
            *(float2*)&C[(size_t)row0 * N + col] = make_float2(v0, v1);
            *(float2*)&C[(size_t)row1 * N + col] = make_float2(v2, v3);
        }
    }
}

// ---------------- fused GEMM(N=128) + residual + LayerNorm [+ q projection] ----------------
// out_row = LN(res_row + A_row@W^T + bias) ; QPROJ=1: q = LNout @ qw^T + qb -> qout (Xout skipped)
// CTA: 128 rows x 128 cols. A is __half [M,K]. grid = M/128.
template<int QPROJ>
__global__ __launch_bounds__(256) void hgemm_ln_kernel(const __half* __restrict__ A,
                                                       const float* __restrict__ W,
                                                       const float* __restrict__ bias,
                                                       const float* __restrict__ res,
                                                       const float* __restrict__ lng,
                                                       const float* __restrict__ lnb,
                                                       float* __restrict__ Xout,
                                                       __half* __restrict__ Xhout,
                                                       const float* __restrict__ qw,
                                                       const float* __restrict__ qb,
                                                       float* __restrict__ qout,
                                                       int M, int K) {
    __shared__ __half As[128][72];
    __shared__ __half Bs[128][72];
    __shared__ float  qws[8][128];
    int tid = threadIdx.x;
    int w = tid >> 5, lane = tid & 31;
    int bm = blockIdx.x * 128;

    if (QPROJ) {  // load 8x128 projection weights
        ((float4*)qws)[tid] = ((const float4*)qw)[tid];
    }

    float acc[16][4];
    #pragma unroll
    for (int j = 0; j < 16; j++)
        #pragma unroll
        for (int c = 0; c < 4; c++) acc[j][c] = 0.f;

    for (int kt = 0; kt < K; kt += 64) {
        #pragma unroll
        for (int i = 0; i < 4; i++) {          // A: 128x64 halves = 1024 uint4
            int idx = tid + i * 256;
            int row = idx >> 3;
            int c8  = (idx & 7) * 8;
            *(uint4*)&As[row][c8] =
                *(const uint4*)&A[(size_t)(bm + row) * K + kt + c8];
        }
        #pragma unroll
        for (int i = 0; i < 8; i++) {          // W: 128x64 floats = 2048 float4
            int idx = tid + i * 256;
            int row = idx >> 4;
            int c4  = (idx & 15) * 4;
            float4 f = *(const float4*)&W[(size_t)row * K + kt + c4];
            __half2* d = (__half2*)&Bs[row][c4];
            d[0] = __floats2half2_rn(f.x, f.y);
            d[1] = __floats2half2_rn(f.z, f.w);
        }
        __syncthreads();

        #pragma unroll
        for (int ks2 = 0; ks2 < 2; ks2++) {
            uint32_t af[2][4];
            #pragma unroll
            for (int s = 0; s < 2; s++) {
                int row = 16 * w + (lane & 15);
                int col = ks2 * 32 + s * 16 + (lane >> 4) * 8;
                LDSM4(af[s][0], af[s][1], af[s][2], af[s][3], smem_u32(&As[row][col]));
            }
            #pragma unroll
            for (int j = 0; j < 16; j++) {
                uint32_t bf[4];
                uint32_t addr = smem_u32(&Bs[8 * j + (lane & 7)][ks2 * 32 + (lane >> 3) * 8]);
                LDSM4(bf[0], bf[1], bf[2], bf[3], addr);
                MMA16816(acc[j], af[0][0], af[0][1], af[0][2], af[0][3], bf[0], bf[1]);
                MMA16816(acc[j], af[1][0], af[1][1], af[1][2], af[1][3], bf[2], bf[3]);
            }
        }
        __syncthreads();
    }

    // ---- epilogue: residual add, LN over 128 cols (one row per quad pair) ----
    int grow0 = bm + 16 * w + (lane >> 2);
    int grow1 = grow0 + 8;
    float s0 = 0.f, q0 = 0.f, s1 = 0.f, q1 = 0.f;
    #pragma unroll
    for (int j = 0; j < 16; j++) {
        int col = 8 * j + 2 * (lane & 3);
        float2 r0 = *(const float2*)&res[(size_t)grow0 * DIMD + col];
        float2 r1 = *(const float2*)&res[(size_t)grow1 * DIMD + col];
        float b0 = bias[col], b1 = bias[col + 1];
        acc[j][0] += b0 + r0.x;  acc[j][1] += b1 + r0.y;
        acc[j][2] += b0 + r1.x;  acc[j][3] += b1 + r1.y;
        s0 += acc[j][0] + acc[j][1];
        q0 += acc[j][0] * acc[j][0] + acc[j][1] * acc[j][1];
        s1 += acc[j][2] + acc[j][3];
        q1 += acc[j][2] * acc[j][2] + acc[j][3] * acc[j][3];
    }
    #pragma unroll
    for (int o = 1; o <= 2; o <<= 1) {
        s0 += __shfl_xor_sync(0xffffffffu, s0, o);
        q0 += __shfl_xor_sync(0xffffffffu, q0, o);
        s1 += __shfl_xor_sync(0xffffffffu, s1, o);
        q1 += __shfl_xor_sync(0xffffffffu, q1, o);
    }
    float mean0 = s0 * (1.f / 128.f), mean1 = s1 * (1.f / 128.f);
    float rs0 = rsqrtf(q0 * (1.f / 128.f) - mean0 * mean0 + 1e-5f);
    float rs1 = rsqrtf(q1 * (1.f / 128.f) - mean1 * mean1 + 1e-5f);

    if (!QPROJ) {
        #pragma unroll
        for (int j = 0; j < 16; j++) {
            int col = 8 * j + 2 * (lane & 3);
            float g0 = lng[col], g1 = lng[col + 1];
            float bb0 = lnb[col], bb1 = lnb[col + 1];
            float v0 = (acc[j][0] - mean0) * rs0 * g0 + bb0;
            float v1 = (acc[j][1] - mean0) * rs0 * g1 + bb1;
            float v2 = (acc[j][2] - mean1) * rs1 * g0 + bb0;
            float v3 = (acc[j][3] - mean1) * rs1 * g1 + bb1;
            *(float2*)&Xout[(size_t)grow0 * DIMD + col] = make_float2(v0, v1);
            *(float2*)&Xout[(size_t)grow1 * DIMD + col] = make_float2(v2, v3);
            *(__half2*)&Xhout[(size_t)grow0 * DIMD + col] = __floats2half2_rn(v0, v1);
            *(__half2*)&Xhout[(size_t)grow1 * DIMD + col] = __floats2half2_rn(v2, v3);
        }
    } else {
        float p0[8], p1[8];
        #pragma unroll
        for (int o = 0; o < 8; o++) { p0[o] = 0.f; p1[o] = 0.f; }
        #pragma unroll
        for (int j = 0; j < 16; j++) {
            int col = 8 * j + 2 * (lane & 3);
            float g0 = lng[col], g1 = lng[col + 1];
            float bb0 = lnb[col], bb1 = lnb[col + 1];
            float v0 = (acc[j][0] - mean0) * rs0 * g0 + bb0;
            float v1 = (acc[j][1] - mean0) * rs0 * g1 + bb1;
            float v2 = (acc[j][2] - mean1) * rs1 * g0 + bb0;
            float v3 = (acc[j][3] - mean1) * rs1 * g1 + bb1;
            #pragma unroll
            for (int o = 0; o < 8; o++) {
                p0[o] += v0 * qws[o][col] + v1 * qws[o][col + 1];
                p1[o] += v2 * qws[o][col] + v3 * qws[o][col + 1];
            }
        }
        #pragma unroll
        for (int o = 0; o < 8; o++) {
            #pragma unroll
            for (int m = 1; m <= 2; m <<= 1) {
                p0[o] += __shfl_xor_sync(0xffffffffu, p0[o], m);
                p1[o] += __shfl_xor_sync(0xffffffffu, p1[o], m);
            }
        }
        int k2 = lane & 3;   // this lane writes outputs 2k2, 2k2+1
        float qb0 = qb[2 * k2], qb1 = qb[2 * k2 + 1];
        *(float2*)&qout[(size_t)grow0 * MODEN + 2 * k2] = make_float2(p0[2 * k2] + qb0, p0[2 * k2 + 1] + qb1);
        *(float2*)&qout[(size_t)grow1 * MODEN + 2 * k2] = make_float2(p1[2 * k2] + qb0, p1[2 * k2 + 1] + qb1);
    }
}

// ---------------- fp16 tensor-core flash attention (fp16 in/out, prefetch) ----------------
__global__ __launch_bounds__(256) void attn_mma_kernel(const __half* __restrict__ QKV,
                                                       __half* __restrict__ CTX) {
    int h = blockIdx.y;
    int b = blockIdx.z;
    int qbase = blockIdx.x * 128;
    int t = threadIdx.x;
    int w = t >> 5, lane = t & 31;

    __shared__ __half Qs[128][40];
    __shared__ __half Ks[64][40];
    __shared__ __half Vs[64][40];

    const __half* base = QKV + (size_t)b * (LL * 384);

    #pragma unroll
    for (int i = 0; i < 2; i++) {
        int idx = t + i * 256;
        int row = idx >> 2;
        int c8  = (idx & 3) * 8;
        *(uint4*)&Qs[row][c8] =
            *(const uint4*)(base + (size_t)(qbase + row) * 384 + h * 32 + c8);
    }

    int tt = t & 127;
    int krow = tt >> 1;
    int kc0  = (tt & 1) * 16;
    int koff = (t < 128) ? 128 : 256;
    uint4 pf0, pf1;
    {
        const uint4* s = (const uint4*)(base + (size_t)krow * 384 + koff + h * 32 + kc0);
        pf0 = s[0]; pf1 = s[1];
    }
    __syncthreads();

    uint32_t qa[2][4];
    {
        int qr = w * 16;
        #pragma unroll
        for (int s = 0; s < 2; s++) {
            int row = qr + (lane & 15);
            int col = s * 16 + (lane >> 4) * 8;
            LDSM4(qa[s][0], qa[s][1], qa[s][2], qa[s][3], smem_u32(&Qs[row][col]));
        }
    }

    float oacc[4][4];
    #pragma unroll
    for (int j = 0; j < 4; j++)
        #pragma unroll
        for (int c = 0; c < 4; c++) oacc[j][c] = 0.f;
    float mrun0 = -1e30f, mrun1 = -1e30f, l0 = 0.f, l1 = 0.f;

    for (int kt = 0; kt < 16; kt++) {
        {
            uint4* d = (uint4*)&((t < 128) ? Ks : Vs)[krow][kc0];
            d[0] = pf0; d[1] = pf1;
        }
        __syncthreads();
        if (kt < 15) {
            const uint4* s = (const uint4*)(base + (size_t)((kt + 1) * 64 + krow) * 384 + koff + h * 32 + kc0);
            pf0 = s[0]; pf1 = s[1];
        }

        float sacc[8][4];
        #pragma unroll
        for (int j = 0; j < 8; j++)
            #pragma unroll
            for (int c = 0; c < 4; c++) sacc[j][c] = 0.f;

        #pragma unroll
        for (int j = 0; j < 8; j++) {
            uint32_t kb[4];
            uint32_t addr = smem_u32(&Ks[8 * j + (lane & 7)][(lane >> 3) * 8]);
            LDSM4(kb[0], kb[1], kb[2], kb[3], addr);
            MMA16816(sacc[j], qa[0][0], qa[0][1], qa[0][2], qa[0][3], kb[0], kb[1]);
            MMA16816(sacc[j], qa[1][0], qa[1][1], qa[1][2], qa[1][3], kb[2], kb[3]);
        }
        #pragma unroll
        for (int j = 0; j < 8; j++)
            #pragma unroll
            for (int c = 0; c < 4; c++) sacc[j][c] *= ATTN_SCALE;

        float mx0 = -1e30f, mx1 = -1e30f;
        #pragma unroll
        for (int j = 0; j < 8; j++) {
            mx0 = fmaxf(mx0, fmaxf(sacc[j][0], sacc[j][1]));
            mx1 = fmaxf(mx1, fmaxf(sacc[j][2], sacc[j][3]));
        }
        #pragma unroll
        for (int o = 1; o <= 2; o <<= 1) {
            mx0 = fmaxf(mx0, __shfl_xor_sync(0xffffffffu, mx0, o));
            mx1 = fmaxf(mx1, __shfl_xor_sync(0xffffffffu, mx1, o));
        }
        float nm0 = fmaxf(mrun0, mx0), nm1 = fmaxf(mrun1, mx1);
        float al0 = __expf(mrun0 - nm0), al1 = __expf(mrun1 - nm1);
        mrun0 = nm0; mrun1 = nm1;

        float rs0 = 0.f, rs1 = 0.f;
        #pragma unroll
        for (int j = 0; j < 8; j++) {
            sacc[j][0] = __expf(sacc[j][0] - nm0); rs0 += sacc[j][0];
            sacc[j][1] = __expf(sacc[j][1] - nm0); rs0 += sacc[j][1];
            sacc[j][2] = __expf(sacc[j][2] - nm1); rs1 += sacc[j][2];
            sacc[j][3] = __expf(sacc[j][3] - nm1); rs1 += sacc[j][3];
        }
        #pragma unroll
        for (int o = 1; o <= 2; o <<= 1) {
            rs0 += __shfl_xor_sync(0xffffffffu, rs0, o);
            rs1 += __shfl_xor_sync(0xffffffffu, rs1, o);
        }
        l0 = l0 * al0 + rs0;
        l1 = l1 * al1 + rs1;
        #pragma unroll
        for (int j = 0; j < 4; j++) {
            oacc[j][0] *= al0; oacc[j][1] *= al0;
            oacc[j][2] *= al1; oacc[j][3] *= al1;
        }

        #pragma unroll
        for (int s = 0; s < 4; s++) {
            uint32_t pa0 = f2h2(sacc[2 * s][0], sacc[2 * s][1]);
            uint32_t pa1 = f2h2(sacc[2 * s][2], sacc[2 * s][3]);
            uint32_t pa2 = f2h2(sacc[2 * s + 1][0], sacc[2 * s + 1][1]);
            uint32_t pa3 = f2h2(sacc[2 * s + 1][2], sacc[2 * s + 1][3]);
            #pragma unroll
            for (int jj = 0; jj < 2; jj++) {
                uint32_t vb[4];
                uint32_t addr = smem_u32(&Vs[16 * s + (lane & 15)][8 * (2 * jj + (lane >> 4))]);
                LDSM4T(vb[0], vb[1], vb[2], vb[3], addr);
                MMA16816(oacc[2 * jj],     pa0, pa1, pa2, pa3, vb[0], vb[1]);
                MMA16816(oacc[2 * jj + 1], pa0, pa1, pa2, pa3, vb[2], vb[3]);
            }
        }
        __syncthreads();
    }

    float inv0 = 1.f / l0, inv1 = 1.f / l1;
    int r0 = qbase + w * 16 + (lane >> 2);
    __half* o0 = CTX + ((size_t)(b * LL + r0)) * DIMD + h * 32 + 2 * (lane & 3);
    __half* o1 = o0 + 8 * DIMD;
    #pragma unroll
    for (int j = 0; j < 4; j++) {
        *(__half2*)(o0 + 8 * j) = __floats2half2_rn(oacc[j][0] * inv0, oacc[j][1] * inv0);
        *(__half2*)(o1 + 8 * j) = __floats2half2_rn(oacc[j][2] * inv1, oacc[j][3] * inv1);
    }
}

// ---------------- small-N GEMM: C[M,8] = A[M,128] @ W[8,128]^T + bias ----------------
__global__ __launch_bounds__(256) void gemm_n8(const float* __restrict__ A,
                                               const float* __restrict__ W,
                                               const float* __restrict__ bias,
                                               float* __restrict__ C) {
    __shared__ float As[32][128];
    __shared__ float Ws[8][128];
    int tid = threadIdx.x;
    size_t row0 = (size_t)blockIdx.x * 32;
    ((float4*)Ws)[tid] = ((const float4*)W)[tid];
    const float4* A4 = (const float4*)(A + row0 * 128);
    #pragma unroll
    for (int s = 0; s < 4; s++) ((float4*)As)[tid + s * 256] = A4[tid + s * 256];
    __syncthreads();
    int r = tid >> 3, j = tid & 7;
    float acc = 0.f;
    #pragma unroll
    for (int k4 = 0; k4 < 32; k4++) {
        float4 a = ((const float4*)As[r])[k4];
        float4 w = ((const float4*)Ws[j])[k4];
        acc += a.x * w.x + a.y * w.y + a.z * w.z + a.w * w.w;
    }
    C[(row0 + r) * MODEN + j] = acc + bias[j];
}

// ---------------- per-(b, mode) max-abs over N nodes ----------------
__global__ void maxabs_kernel(const float* __restrict__ phi, float* __restrict__ gmax) {
    int b = blockIdx.x;
    int n = threadIdx.x; // 256
    __shared__ float sm[256][8];
    #pragma unroll
    for (int j = 0; j < 8; j++)
        sm[n][j] = fabsf(phi[((size_t)b * NN + n) * MODEN + j]);
    __syncthreads();
    for (int s = 128; s > 0; s >>= 1) {
        if (n < s) {
            #pragma unroll
            for (int j = 0; j < 8; j++) sm[n][j] = fmaxf(sm[n][j], sm[n + s][j]);
        }
        __syncthreads();
    }
    if (n < 8) gmax[b * 8 + n] = sm[0][n];
}

__global__ void phinorm_kernel(const float* __restrict__ phi, const float* __restrict__ gmax,
                               float* __restrict__ out) {
    int i = blockIdx.x * 256 + threadIdx.x;
    int b = i >> 11;
    int j = i & 7;
    out[i] = phi[i] / gmax[b * 8 + j];
}

// ---------------- launch ----------------
extern "C" void kernel_launch(void* const* d_in, const int* in_sizes, int n_in,
                              void* d_out, int out_size) {
    (void)in_sizes; (void)n_in; (void)out_size;
    const float* acc_Y      = (const float*)d_in[0];
    const float* proj_in_w  = (const float*)d_in[2];
    const float* proj_in_b  = (const float*)d_in[3];
    const float* attn_in_w  = (const float*)d_in[4];
    const float* attn_in_b  = (const float*)d_in[5];
    const float* attn_out_w = (const float*)d_in[6];
    const float* attn_out_b = (const float*)d_in[7];
    const float* ln1_g      = (const float*)d_in[8];
    const float* ln1_b      = (const float*)d_in[9];
    const float* ff1_w      = (const float*)d_in[10];
    const float* ff1_b      = (const float*)d_in[11];
    const float* ff2_w      = (const float*)d_in[12];
    const float* ff2_b      = (const float*)d_in[13];
    const float* ln2_g      = (const float*)d_in[14];
    const float* ln2_b      = (const float*)d_in[15];
    const float* proj_out_w = (const float*)d_in[16];
    const float* proj_out_b = (const float*)d_in[17];
    const float* mlp1_w     = (const float*)d_in[18];
    const float* mlp1_b     = (const float*)d_in[19];
    const float* mlp2_w     = (const float*)d_in[20];
    const float* mlp2_b     = (const float*)d_in[21];
    const float* mlp3_w     = (const float*)d_in[22];
    const float* mlp3_b     = (const float*)d_in[23];
    float* out = (float*)d_out;

    float  *pX, *pX2, *pH1, *pH2, *pPHI, *pMAX;
    __half *pXh, *pX2h, *pQKVh, *pCTXh, *pTMPh;
    cudaGetSymbolAddress((void**)&pX,    g_X);
    cudaGetSymbolAddress((void**)&pXh,   g_Xh);
    cudaGetSymbolAddress((void**)&pX2,   g_X2);
    cudaGetSymbolAddress((void**)&pX2h,  g_X2h);
    cudaGetSymbolAddress((void**)&pQKVh, g_QKVh);
    cudaGetSymbolAddress((void**)&pCTXh, g_CTXh);
    cudaGetSymbolAddress((void**)&pTMPh, g_TMPh);
    cudaGetSymbolAddress((void**)&pH1,   g_H1);
    cudaGetSymbolAddress((void**)&pH2,   g_H2);
    cudaGetSymbolAddress((void**)&pPHI,  g_PHI);
    cudaGetSymbolAddress((void**)&pMAX,  g_MAX);

    // ===== q path (6 launches) =====
    proj_in_kernel<<<MQ, 128>>>(acc_Y, proj_in_w, proj_in_b, pX, pXh);
    hgemm_kernel<0,1,1><<<dim3(6, MQ / 128), 256>>>(pXh, attn_in_w, attn_in_b, pQKVh, MQ, 384, 128);
    attn_mma_kernel<<<dim3(LL / 128, HH, BB), 256>>>(pQKVh, pCTXh);
    // fused: X2 = LN1(X + attn_out(CTX))
    hgemm_ln_kernel<0><<<MQ / 128, 256>>>(pCTXh, attn_out_w, attn_out_b, pX, ln1_g, ln1_b,
                                          pX2, pX2h, nullptr, nullptr, nullptr, MQ, 128);
    hgemm_kernel<1,1,1><<<dim3(4, MQ / 128), 256>>>(pX2h, ff1_w, ff1_b, pTMPh, MQ, 256, 128);
    // fused: q = LN2(X2 + ff2(TMP)) @ proj_out^T + b  -> out
    hgemm_ln_kernel<1><<<MQ / 128, 256>>>(pTMPh, ff2_w, ff2_b, pX2, ln2_g, ln2_b,
                                          nullptr, nullptr, proj_out_w, proj_out_b, out, MQ, 256);

    // ===== phi path =====
    hgemm_kernel<2,0,0><<<dim3(2, MP / 128), 256>>>(acc_Y, mlp1_w, mlp1_b, pH1, MP, 128, 1024);
    hgemm_kernel<2,0,0><<<dim3(2, MP / 128), 256>>>(pH1, mlp2_w, mlp2_b, pH2, MP, 128, 128);
    hgemm_kernel<2,0,0><<<dim3(2, MP / 128), 256>>>(pH2, mlp2_w, mlp2_b, pH1, MP, 128, 128);
    gemm_n8<<<MP / 32, 256>>>(pH1, mlp3_w, mlp3_b, pPHI);
    maxabs_kernel<<<BB, 256>>>(pPHI, pMAX);
    phinorm_kernel<<<(MP * MODEN) / 256, 256>>>(pPHI, pMAX, out + MQ * MODEN);
}

// round 13
// speedup vs baseline: 4.2402x; 1.0596x over previous
#include <cuda_runtime.h>
#include <cuda_fp16.h>
#include <cuda_bf16.h>
#include <math.h>
#include <stdint.h>

// ---------------- problem constants ----------------
#define BB    32
#define NN    256
#define LL    1024
#define DIMD  128
#define MODEN 8
#define HH    4
#define DHD   32
#define FFD   256
#define MQ    (BB*LL)    // 32768 rows, q path
#define MP    (BB*NN)    // 8192 rows, phi path
#define ATTN_SCALE 0.17677669529663687f  // 1/sqrt(32)

// half-weight buffer offsets
#define W_ATTNIN  0                      // 384*128 = 49152
#define W_ATTNOUT 49152                  // 128*128 = 16384
#define W_FF1     65536                  // 256*128 = 32768
#define W_FF2     98304                  // 128*256 = 32768
#define W_MLP1    131072                 // 128*1024 = 131072
#define W_MLP2    262144                 // 128*128 = 16384
#define W_TOTAL   278528

// ---------------- scratch (device globals; no allocation allowed) ----------------
__device__ float  g_X   [MQ * DIMD];
__device__ __half g_Xh  [MQ * DIMD];
__device__ float  g_X2  [MQ * DIMD];
__device__ __half g_X2h [MQ * DIMD];
__device__ __half g_QKVh[MQ * 3 * DIMD];
__device__ __half g_CTXh[MQ * DIMD];
__device__ __half g_TMPh[MQ * FFD];
__device__ float  g_PHI [MP * MODEN];
__device__ __half g_Wh  [W_TOTAL];

// ---------------- helpers ----------------
__device__ __forceinline__ uint32_t smem_u32(const void* p) {
    return (uint32_t)__cvta_generic_to_shared(p);
}

__device__ __forceinline__ uint32_t f2h2(float a, float b) {
    __half2 h = __floats2half2_rn(a, b);
    return *reinterpret_cast<uint32_t*>(&h);
}

#define LDSM4(r0,r1,r2,r3,addr) \
    asm volatile("ldmatrix.sync.aligned.m8n8.x4.shared.b16 {%0,%1,%2,%3},[%4];" \
                 : "=r"(r0),"=r"(r1),"=r"(r2),"=r"(r3) : "r"(addr))
#define LDSM4T(r0,r1,r2,r3,addr) \
    asm volatile("ldmatrix.sync.aligned.m8n8.x4.trans.shared.b16 {%0,%1,%2,%3},[%4];" \
                 : "=r"(r0),"=r"(r1),"=r"(r2),"=r"(r3) : "r"(addr))
#define MMA16816(c,a0,a1,a2,a3,b0,b1) \
    asm volatile("mma.sync.aligned.m16n8k16.row.col.f32.f16.f16.f32 " \
                 "{%0,%1,%2,%3},{%4,%5,%6,%7},{%8,%9},{%0,%1,%2,%3};" \
                 : "+f"(c[0]),"+f"(c[1]),"+f"(c[2]),"+f"(c[3]) \
                 : "r"(a0),"r"(a1),"r"(a2),"r"(a3),"r"(b0),"r"(b1))

// ---------------- one-shot weight conversion fp32 -> fp16 ----------------
__global__ void convw_kernel(const float* __restrict__ aw, const float* __restrict__ ow,
                             const float* __restrict__ f1, const float* __restrict__ f2,
                             const float* __restrict__ m1, const float* __restrict__ m2,
                             __half* __restrict__ dst) {
    int i = blockIdx.x * 256 + threadIdx.x;   // 0 .. W_TOTAL-1
    float v;
    if      (i < W_ATTNOUT) v = aw[i];
    else if (i < W_FF1)     v = ow[i - W_ATTNOUT];
    else if (i < W_FF2)     v = f1[i - W_FF1];
    else if (i < W_MLP1)    v = f2[i - W_FF2];
    else if (i < W_MLP2)    v = m1[i - W_MLP1];
    else                    v = m2[i - W_MLP2];
    dst[i] = __float2half(v);
}

// ---------------- proj_in: writes fp32 + fp16 ----------------
__global__ void proj_in_kernel(const float* __restrict__ Y,
                               const float* __restrict__ w,
                               const float* __restrict__ bias,
                               float* __restrict__ X,
                               __half* __restrict__ Xh) {
    int r = blockIdx.x;
    int b = r >> 10;
    int l = r & 1023;
    int t = threadIdx.x;              // 128
    __shared__ float xs[7];
    if (t < 7) xs[t] = Y[((size_t)b * NN + 2 + t) * LL + l];
    __syncthreads();
    float acc = bias[t];
    #pragma unroll
    for (int j = 0; j < 7; j++) acc += xs[j] * w[t * 7 + j];
    X[(size_t)r * DIMD + t]  = acc;
    Xh[(size_t)r * DIMD + t] = __float2half(acc);
}

// ---------------- fp16 tensor-core GEMM (N-tile 64), half A + half W ----------------
// C[M,N] = A[M,K] @ W[N,K]^T + bias. ACT: 0 none, 1 relu. CHALF: C half.
template<int ACT, int CHALF>
__global__ __launch_bounds__(256) void hgemm_kernel(const __half* __restrict__ A,
                                                    const __half* __restrict__ W,
                                                    const float* __restrict__ bias,
                                                    void* __restrict__ Cv,
                                                    int M, int N, int K) {
    __shared__ __half As[128][72];
    __shared__ __half Bs[64][72];
    int tid = threadIdx.x;
    int w = tid >> 5, lane = tid & 31;
    int bm = blockIdx.y * 128;
    int bn = blockIdx.x * 64;

    float acc[8][4];
    #pragma unroll
    for (int j = 0; j < 8; j++)
        #pragma unroll
        for (int c = 0; c < 4; c++) acc[j][c] = 0.f;

    for (int kt = 0; kt < K; kt += 64) {
        #pragma unroll
        for (int i = 0; i < 4; i++) {          // A: 128x64 halves = 1024 uint4
            int idx = tid + i * 256;
            int row = idx >> 3;
            int c8  = (idx & 7) * 8;
            *(uint4*)&As[row][c8] = *(const uint4*)&A[(size_t)(bm + row) * K + kt + c8];
        }
        #pragma unroll
        for (int i = 0; i < 2; i++) {          // W: 64x64 halves = 512 uint4
            int idx = tid + i * 256;
            int row = idx >> 3;
            int c8  = (idx & 7) * 8;
            *(uint4*)&Bs[row][c8] = *(const uint4*)&W[(size_t)(bn + row) * K + kt + c8];
        }
        __syncthreads();

        #pragma unroll
        for (int ks2 = 0; ks2 < 2; ks2++) {
            uint32_t af[2][4];
            #pragma unroll
            for (int s = 0; s < 2; s++) {
                int row = 16 * w + (lane & 15);
                int col = ks2 * 32 + s * 16 + (lane >> 4) * 8;
                LDSM4(af[s][0], af[s][1], af[s][2], af[s][3], smem_u32(&As[row][col]));
            }
            #pragma unroll
            for (int j = 0; j < 8; j++) {
                uint32_t bf[4];
                uint32_t addr = smem_u32(&Bs[8 * j + (lane & 7)][ks2 * 32 + (lane >> 3) * 8]);
                LDSM4(bf[0], bf[1], bf[2], bf[3], addr);
                MMA16816(acc[j], af[0][0], af[0][1], af[0][2], af[0][3], bf[0], bf[1]);
                MMA16816(acc[j], af[1][0], af[1][1], af[1][2], af[1][3], bf[2], bf[3]);
            }
        }
        __syncthreads();
    }

    int row0 = bm + 16 * w + (lane >> 2);
    int row1 = row0 + 8;
    #pragma unroll
    for (int j = 0; j < 8; j++) {
        int col = bn + 8 * j + 2 * (lane & 3);
        float b0 = bias[col], b1 = bias[col + 1];
        float v0 = acc[j][0] + b0, v1 = acc[j][1] + b1;
        float v2 = acc[j][2] + b0, v3 = acc[j][3] + b1;
        if (ACT == 1) { v0 = fmaxf(v0, 0.f); v1 = fmaxf(v1, 0.f); v2 = fmaxf(v2, 0.f); v3 = fmaxf(v3, 0.f); }
        if (CHALF) {
            __half* C = (__half*)Cv;
            *(__half2*)&C[(size_t)row0 * N + col] = __floats2half2_rn(v0, v1);
            *(__half2*)&C[(size_t)row1 * N + col] = __floats2half2_rn(v2, v3);
        } else {
            float* C = (float*)Cv;
            *(float2*)&C[(size_t)row0 * N + col] = make_float2(v0, v1);
            *(float2*)&C[(size_t)row1 * N + col] = make_float2(v2, v3);
        }
    }
}

// ---------------- fused GEMM(N=128) + residual + LayerNorm [+ q projection] ----------------
// out_row = LN(res_row + A_row@W^T + bias). QPROJ=1: q = LNout @ qw^T + qb -> qout.
template<int QPROJ>
__global__ __launch_bounds__(256) void hgemm_ln_kernel(const __half* __restrict__ A,
                                                       const __half* __restrict__ W,
                                                       const float* __restrict__ bias,
                                                       const float* __restrict__ res,
                                                       const float* __restrict__ lng,
                                                       const float* __restrict__ lnb,
                                                       float* __restrict__ Xout,
                                                       __half* __restrict__ Xhout,
                                                       const float* __restrict__ qw,
                                                       const float* __restrict__ qb,
                                                       float* __restrict__ qout,
                                                       int M, int K) {
    __shared__ __half As[128][72];
    __shared__ __half Bs[128][72];
    __shared__ float  qws[8][128];
    int tid = threadIdx.x;
    int w = tid >> 5, lane = tid & 31;
    int bm = blockIdx.x * 128;

    if (QPROJ) {
        ((float4*)qws)[tid] = ((const float4*)qw)[tid];
    }

    float acc[16][4];
    #pragma unroll
    for (int j = 0; j < 16; j++)
        #pragma unroll
        for (int c = 0; c < 4; c++) acc[j][c] = 0.f;

    for (int kt = 0; kt < K; kt += 64) {
        #pragma unroll
        for (int i = 0; i < 4; i++) {          // A: 128x64 halves
            int idx = tid + i * 256;
            int row = idx >> 3;
            int c8  = (idx & 7) * 8;
            *(uint4*)&As[row][c8] = *(const uint4*)&A[(size_t)(bm + row) * K + kt + c8];
        }
        #pragma unroll
        for (int i = 0; i < 4; i++) {          // W: 128x64 halves
            int idx = tid + i * 256;
            int row = idx >> 3;
            int c8  = (idx & 7) * 8;
            *(uint4*)&Bs[row][c8] = *(const uint4*)&W[(size_t)row * K + kt + c8];
        }
        __syncthreads();

        #pragma unroll
        for (int ks2 = 0; ks2 < 2; ks2++) {
            uint32_t af[2][4];
            #pragma unroll
            for (int s = 0; s < 2; s++) {
                int row = 16 * w + (lane & 15);
                int col = ks2 * 32 + s * 16 + (lane >> 4) * 8;
                LDSM4(af[s][0], af[s][1], af[s][2], af[s][3], smem_u32(&As[row][col]));
            }
            #pragma unroll
            for (int j = 0; j < 16; j++) {
                uint32_t bf[4];
                uint32_t addr = smem_u32(&Bs[8 * j + (lane & 7)][ks2 * 32 + (lane >> 3) * 8]);
                LDSM4(bf[0], bf[1], bf[2], bf[3], addr);
                MMA16816(acc[j], af[0][0], af[0][1], af[0][2], af[0][3], bf[0], bf[1]);
                MMA16816(acc[j], af[1][0], af[1][1], af[1][2], af[1][3], bf[2], bf[3]);
            }
        }
        __syncthreads();
    }

    int grow0 = bm + 16 * w + (lane >> 2);
    int grow1 = grow0 + 8;
    float s0 = 0.f, q0 = 0.f, s1 = 0.f, q1 = 0.f;
    #pragma unroll
    for (int j = 0; j < 16; j++) {
        int col = 8 * j + 2 * (lane & 3);
        float2 r0 = *(const float2*)&res[(size_t)grow0 * DIMD + col];
        float2 r1 = *(const float2*)&res[(size_t)grow1 * DIMD + col];
        float b0 = bias[col], b1 = bias[col + 1];
        acc[j][0] += b0 + r0.x;  acc[j][1] += b1 + r0.y;
        acc[j][2] += b0 + r1.x;  acc[j][3] += b1 + r1.y;
        s0 += acc[j][0] + acc[j][1];
        q0 += acc[j][0] * acc[j][0] + acc[j][1] * acc[j][1];
        s1 += acc[j][2] + acc[j][3];
        q1 += acc[j][2] * acc[j][2] + acc[j][3] * acc[j][3];
    }
    #pragma unroll
    for (int o = 1; o <= 2; o <<= 1) {
        s0 += __shfl_xor_sync(0xffffffffu, s0, o);
        q0 += __shfl_xor_sync(0xffffffffu, q0, o);
        s1 += __shfl_xor_sync(0xffffffffu, s1, o);
        q1 += __shfl_xor_sync(0xffffffffu, q1, o);
    }
    float mean0 = s0 * (1.f / 128.f), mean1 = s1 * (1.f / 128.f);
    float rs0 = rsqrtf(q0 * (1.f / 128.f) - mean0 * mean0 + 1e-5f);
    float rs1 = rsqrtf(q1 * (1.f / 128.f) - mean1 * mean1 + 1e-5f);

    if (!QPROJ) {
        #pragma unroll
        for (int j = 0; j < 16; j++) {
            int col = 8 * j + 2 * (lane & 3);
            float g0 = lng[col], g1 = lng[col + 1];
            float bb0 = lnb[col], bb1 = lnb[col + 1];
            float v0 = (acc[j][0] - mean0) * rs0 * g0 + bb0;
            float v1 = (acc[j][1] - mean0) * rs0 * g1 + bb1;
            float v2 = (acc[j][2] - mean1) * rs1 * g0 + bb0;
            float v3 = (acc[j][3] - mean1) * rs1 * g1 + bb1;
            *(float2*)&Xout[(size_t)grow0 * DIMD + col] = make_float2(v0, v1);
            *(float2*)&Xout[(size_t)grow1 * DIMD + col] = make_float2(v2, v3);
            *(__half2*)&Xhout[(size_t)grow0 * DIMD + col] = __floats2half2_rn(v0, v1);
            *(__half2*)&Xhout[(size_t)grow1 * DIMD + col] = __floats2half2_rn(v2, v3);
        }
    } else {
        float p0[8], p1[8];
        #pragma unroll
        for (int o = 0; o < 8; o++) { p0[o] = 0.f; p1[o] = 0.f; }
        #pragma unroll
        for (int j = 0; j < 16; j++) {
            int col = 8 * j + 2 * (lane & 3);
            float g0 = lng[col], g1 = lng[col + 1];
            float bb0 = lnb[col], bb1 = lnb[col + 1];
            float v0 = (acc[j][0] - mean0) * rs0 * g0 + bb0;
            float v1 = (acc[j][1] - mean0) * rs0 * g1 + bb1;
            float v2 = (acc[j][2] - mean1) * rs1 * g0 + bb0;
            float v3 = (acc[j][3] - mean1) * rs1 * g1 + bb1;
            #pragma unroll
            for (int o = 0; o < 8; o++) {
                p0[o] += v0 * qws[o][col] + v1 * qws[o][col + 1];
                p1[o] += v2 * qws[o][col] + v3 * qws[o][col + 1];
            }
        }
        #pragma unroll
        for (int o = 0; o < 8; o++) {
            #pragma unroll
            for (int m = 1; m <= 2; m <<= 1) {
                p0[o] += __shfl_xor_sync(0xffffffffu, p0[o], m);
                p1[o] += __shfl_xor_sync(0xffffffffu, p1[o], m);
            }
        }
        int k2 = lane & 3;
        float qb0 = qb[2 * k2], qb1 = qb[2 * k2 + 1];
        *(float2*)&qout[(size_t)grow0 * MODEN + 2 * k2] = make_float2(p0[2 * k2] + qb0, p0[2 * k2 + 1] + qb1);
        *(float2*)&qout[(size_t)grow1 * MODEN + 2 * k2] = make_float2(p1[2 * k2] + qb0, p1[2 * k2 + 1] + qb1);
    }
}

// ---------------- fused phi MLP: tanh(mlp1) -> tanh(mlp2) -> tanh(mlp2) -> mlp3 ----------------
// One CTA = 128 rows, fully on-chip chaining via in-register fragment repack.
__global__ __launch_bounds__(256) void phi_fused_kernel(const float* __restrict__ Y,
                                                        const __half* __restrict__ W1h,
                                                        const float* __restrict__ b1,
                                                        const __half* __restrict__ W2h,
                                                        const float* __restrict__ b2,
                                                        const float* __restrict__ W3,
                                                        const float* __restrict__ b3,
                                                        float* __restrict__ PHI) {
    __shared__ __half As[128][72];
    __shared__ __half Bs[128][72];
    __shared__ float  w3s[8][128];
    int tid = threadIdx.x;
    int w = tid >> 5, lane = tid & 31;
    int bm = blockIdx.x * 128;

    ((float4*)w3s)[tid] = ((const float4*)W3)[tid];   // 8x128 = 256 float4

    float acc[16][4];
    #pragma unroll
    for (int j = 0; j < 16; j++)
        #pragma unroll
        for (int c = 0; c < 4; c++) acc[j][c] = 0.f;

    // ===== mlp1: K=1024, A = Y fp32 (convert), W1 half =====
    for (int kt = 0; kt < 1024; kt += 64) {
        #pragma unroll
        for (int i = 0; i < 8; i++) {
            int idx = tid + i * 256;
            int row = idx >> 4;
            int c4  = (idx & 15) * 4;
            float4 f = *(const float4*)&Y[(size_t)(bm + row) * 1024 + kt + c4];
            __half2* d = (__half2*)&As[row][c4];
            d[0] = __floats2half2_rn(f.x, f.y);
            d[1] = __floats2half2_rn(f.z, f.w);
        }
        #pragma unroll
        for (int i = 0; i < 4; i++) {
            int idx = tid + i * 256;
            int row = idx >> 3;
            int c8  = (idx & 7) * 8;
            *(uint4*)&Bs[row][c8] = *(const uint4*)&W1h[(size_t)row * 1024 + kt + c8];
        }
        __syncthreads();
        #pragma unroll
        for (int ks2 = 0; ks2 < 2; ks2++) {
            uint32_t af[2][4];
            #pragma unroll
            for (int s = 0; s < 2; s++) {
                int row = 16 * w + (lane & 15);
                int col = ks2 * 32 + s * 16 + (lane >> 4) * 8;
                LDSM4(af[s][0], af[s][1], af[s][2], af[s][3], smem_u32(&As[row][col]));
            }
            #pragma unroll
            for (int j = 0; j < 16; j++) {
                uint32_t bf[4];
                uint32_t addr = smem_u32(&Bs[8 * j + (lane & 7)][ks2 * 32 + (lane >> 3) * 8]);
                LDSM4(bf[0], bf[1], bf[2], bf[3], addr);
                MMA16816(acc[j], af[0][0], af[0][1], af[0][2], af[0][3], bf[0], bf[1]);
                MMA16816(acc[j], af[1][0], af[1][1], af[1][2], af[1][3], bf[2], bf[3]);
            }
        }
        __syncthreads();
    }

    // bias + tanh -> A fragments (8 chunks of k=16)
    uint32_t af2[8][4];
    #pragma unroll
    for (int j = 0; j < 16; j++) {
        int col = 8 * j + 2 * (lane & 3);
        float b0 = b1[col], bb1 = b1[col + 1];
        acc[j][0] = tanhf(acc[j][0] + b0);
        acc[j][1] = tanhf(acc[j][1] + bb1);
        acc[j][2] = tanhf(acc[j][2] + b0);
        acc[j][3] = tanhf(acc[j][3] + bb1);
    }
    #pragma unroll
    for (int s = 0; s < 8; s++) {
        af2[s][0] = f2h2(acc[2 * s][0],     acc[2 * s][1]);
        af2[s][1] = f2h2(acc[2 * s][2],     acc[2 * s][3]);
        af2[s][2] = f2h2(acc[2 * s + 1][0], acc[2 * s + 1][1]);
        af2[s][3] = f2h2(acc[2 * s + 1][2], acc[2 * s + 1][3]);
    }

    // ===== load W2 once: chunk k0..63 -> As, k64..127 -> Bs =====
    #pragma unroll
    for (int i = 0; i < 4; i++) {
        int idx = tid + i * 256;
        int row = idx >> 3;
        int c8  = (idx & 7) * 8;
        *(uint4*)&As[row][c8] = *(const uint4*)&W2h[(size_t)row * 128 + c8];
        *(uint4*)&Bs[row][c8] = *(const uint4*)&W2h[(size_t)row * 128 + 64 + c8];
    }
    __syncthreads();

    // ===== two mlp2 layers =====
    #pragma unroll
    for (int layer = 0; layer < 2; layer++) {
        #pragma unroll
        for (int j = 0; j < 16; j++)
            #pragma unroll
            for (int c = 0; c < 4; c++) acc[j][c] = 0.f;
        #pragma unroll
        for (int sub = 0; sub < 4; sub++) {          // 32-k subchunks
            int co = (sub & 1) * 32;
            #pragma unroll
            for (int j = 0; j < 16; j++) {
                uint32_t bf[4];
                uint32_t addr = (sub < 2)
                    ? smem_u32(&As[8 * j + (lane & 7)][co + (lane >> 3) * 8])
                    : smem_u32(&Bs[8 * j + (lane & 7)][co + (lane >> 3) * 8]);
                LDSM4(bf[0], bf[1], bf[2], bf[3], addr);
                MMA16816(acc[j], af2[2 * sub][0], af2[2 * sub][1], af2[2 * sub][2], af2[2 * sub][3], bf[0], bf[1]);
                MMA16816(acc[j], af2[2 * sub + 1][0], af2[2 * sub + 1][1], af2[2 * sub + 1][2], af2[2 * sub + 1][3], bf[2], bf[3]);
            }
        }
        #pragma unroll
        for (int j = 0; j < 16; j++) {
            int col = 8 * j + 2 * (lane & 3);
            float b0 = b2[col], bb1 = b2[col + 1];
            acc[j][0] = tanhf(acc[j][0] + b0);
            acc[j][1] = tanhf(acc[j][1] + bb1);
            acc[j][2] = tanhf(acc[j][2] + b0);
            acc[j][3] = tanhf(acc[j][3] + bb1);
        }
        if (layer == 0) {
            #pragma unroll
            for (int s = 0; s < 8; s++) {
                af2[s][0] = f2h2(acc[2 * s][0],     acc[2 * s][1]);
                af2[s][1] = f2h2(acc[2 * s][2],     acc[2 * s][3]);
                af2[s][2] = f2h2(acc[2 * s + 1][0], acc[2 * s + 1][1]);
                af2[s][3] = f2h2(acc[2 * s + 1][2], acc[2 * s + 1][3]);
            }
        }
    }

    // ===== mlp3: 8 outputs via per-thread dots + quad reduce =====
    float p0[8], p1[8];
    #pragma unroll
    for (int o = 0; o < 8; o++) { p0[o] = 0.f; p1[o] = 0.f; }
    #pragma unroll
    for (int j = 0; j < 16; j++) {
        int col = 8 * j + 2 * (lane & 3);
        #pragma unroll
        for (int o = 0; o < 8; o++) {
            p0[o] += acc[j][0] * w3s[o][col] + acc[j][1] * w3s[o][col + 1];
            p1[o] += acc[j][2] * w3s[o][col] + acc[j][3] * w3s[o][col + 1];
        }
    }
    #pragma unroll
    for (int o = 0; o < 8; o++) {
        #pragma unroll
        for (int m = 1; m <= 2; m <<= 1) {
            p0[o] += __shfl_xor_sync(0xffffffffu, p0[o], m);
            p1[o] += __shfl_xor_sync(0xffffffffu, p1[o], m);
        }
    }
    int grow0 = bm + 16 * w + (lane >> 2);
    int grow1 = grow0 + 8;
    int k2 = lane & 3;
    float b30 = b3[2 * k2], b31 = b3[2 * k2 + 1];
    *(float2*)&PHI[(size_t)grow0 * MODEN + 2 * k2] = make_float2(p0[2 * k2] + b30, p0[2 * k2 + 1] + b31);
    *(float2*)&PHI[(size_t)grow1 * MODEN + 2 * k2] = make_float2(p1[2 * k2] + b30, p1[2 * k2 + 1] + b31);
}

// ---------------- fp16 tensor-core flash attention (fp16 in/out, prefetch) ----------------
__global__ __launch_bounds__(256) void attn_mma_kernel(const __half* __restrict__ QKV,
                                                       __half* __restrict__ CTX) {
    int h = blockIdx.y;
    int b = blockIdx.z;
    int qbase = blockIdx.x * 128;
    int t = threadIdx.x;
    int w = t >> 5, lane = t & 31;

    __shared__ __half Qs[128][40];
    __shared__ __half Ks[64][40];
    __shared__ __half Vs[64][40];

    const __half* base = QKV + (size_t)b * (LL * 384);

    #pragma unroll
    for (int i = 0; i < 2; i++) {
        int idx = t + i * 256;
        int row = idx >> 2;
        int c8  = (idx & 3) * 8;
        *(uint4*)&Qs[row][c8] =
            *(const uint4*)(base + (size_t)(qbase + row) * 384 + h * 32 + c8);
    }

    int tt = t & 127;
    int krow = tt >> 1;
    int kc0  = (tt & 1) * 16;
    int koff = (t < 128) ? 128 : 256;
    uint4 pf0, pf1;
    {
        const uint4* s = (const uint4*)(base + (size_t)krow * 384 + koff + h * 32 + kc0);
        pf0 = s[0]; pf1 = s[1];
    }
    __syncthreads();

    uint32_t qa[2][4];
    {
        int qr = w * 16;
        #pragma unroll
        for (int s = 0; s < 2; s++) {
            int row = qr + (lane & 15);
            int col = s * 16 + (lane >> 4) * 8;
            LDSM4(qa[s][0], qa[s][1], qa[s][2], qa[s][3], smem_u32(&Qs[row][col]));
        }
    }

    float oacc[4][4];
    #pragma unroll
    for (int j = 0; j < 4; j++)
        #pragma unroll
        for (int c = 0; c < 4; c++) oacc[j][c] = 0.f;
    float mrun0 = -1e30f, mrun1 = -1e30f, l0 = 0.f, l1 = 0.f;

    for (int kt = 0; kt < 16; kt++) {
        {
            uint4* d = (uint4*)&((t < 128) ? Ks : Vs)[krow][kc0];
            d[0] = pf0; d[1] = pf1;
        }
        __syncthreads();
        if (kt < 15) {
            const uint4* s = (const uint4*)(base + (size_t)((kt + 1) * 64 + krow) * 384 + koff + h * 32 + kc0);
            pf0 = s[0]; pf1 = s[1];
        }

        float sacc[8][4];
        #pragma unroll
        for (int j = 0; j < 8; j++)
            #pragma unroll
            for (int c = 0; c < 4; c++) sacc[j][c] = 0.f;

        #pragma unroll
        for (int j = 0; j < 8; j++) {
            uint32_t kb[4];
            uint32_t addr = smem_u32(&Ks[8 * j + (lane & 7)][(lane >> 3) * 8]);
            LDSM4(kb[0], kb[1], kb[2], kb[3], addr);
            MMA16816(sacc[j], qa[0][0], qa[0][1], qa[0][2], qa[0][3], kb[0], kb[1]);
            MMA16816(sacc[j], qa[1][0], qa[1][1], qa[1][2], qa[1][3], kb[2], kb[3]);
        }
        #pragma unroll
        for (int j = 0; j < 8; j++)
            #pragma unroll
            for (int c = 0; c < 4; c++) sacc[j][c] *= ATTN_SCALE;

        float mx0 = -1e30f, mx1 = -1e30f;
        #pragma unroll
        for (int j = 0; j < 8; j++) {
            mx0 = fmaxf(mx0, fmaxf(sacc[j][0], sacc[j][1]));
            mx1 = fmaxf(mx1, fmaxf(sacc[j][2], sacc[j][3]));
        }
        #pragma unroll
        for (int o = 1; o <= 2; o <<= 1) {
            mx0 = fmaxf(mx0, __shfl_xor_sync(0xffffffffu, mx0, o));
            mx1 = fmaxf(mx1, __shfl_xor_sync(0xffffffffu, mx1, o));
        }
        float nm0 = fmaxf(mrun0, mx0), nm1 = fmaxf(mrun1, mx1);
        float al0 = __expf(mrun0 - nm0), al1 = __expf(mrun1 - nm1);
        mrun0 = nm0; mrun1 = nm1;

        float rs0 = 0.f, rs1 = 0.f;
        #pragma unroll
        for (int j = 0; j < 8; j++) {
            sacc[j][0] = __expf(sacc[j][0] - nm0); rs0 += sacc[j][0];
            sacc[j][1] = __expf(sacc[j][1] - nm0); rs0 += sacc[j][1];
            sacc[j][2] = __expf(sacc[j][2] - nm1); rs1 += sacc[j][2];
            sacc[j][3] = __expf(sacc[j][3] - nm1); rs1 += sacc[j][3];
        }
        #pragma unroll
        for (int o = 1; o <= 2; o <<= 1) {
            rs0 += __shfl_xor_sync(0xffffffffu, rs0, o);
            rs1 += __shfl_xor_sync(0xffffffffu, rs1, o);
        }
        l0 = l0 * al0 + rs0;
        l1 = l1 * al1 + rs1;
        #pragma unroll
        for (int j = 0; j < 4; j++) {
            oacc[j][0] *= al0; oacc[j][1] *= al0;
            oacc[j][2] *= al1; oacc[j][3] *= al1;
        }

        #pragma unroll
        for (int s = 0; s < 4; s++) {
            uint32_t pa0 = f2h2(sacc[2 * s][0], sacc[2 * s][1]);
            uint32_t pa1 = f2h2(sacc[2 * s][2], sacc[2 * s][3]);
            uint32_t pa2 = f2h2(sacc[2 * s + 1][0], sacc[2 * s + 1][1]);
            uint32_t pa3 = f2h2(sacc[2 * s + 1][2], sacc[2 * s + 1][3]);
            #pragma unroll
            for (int jj = 0; jj < 2; jj++) {
                uint32_t vb[4];
                uint32_t addr = smem_u32(&Vs[16 * s + (lane & 15)][8 * (2 * jj + (lane >> 4))]);
                LDSM4T(vb[0], vb[1], vb[2], vb[3], addr);
                MMA16816(oacc[2 * jj],     pa0, pa1, pa2, pa3, vb[0], vb[1]);
                MMA16816(oacc[2 * jj + 1], pa0, pa1, pa2, pa3, vb[2], vb[3]);
            }
        }
        __syncthreads();
    }

    float inv0 = 1.f / l0, inv1 = 1.f / l1;
    int r0 = qbase + w * 16 + (lane >> 2);
    __half* o0 = CTX + ((size_t)(b * LL + r0)) * DIMD + h * 32 + 2 * (lane & 3);
    __half* o1 = o0 + 8 * DIMD;
    #pragma unroll
    for (int j = 0; j < 4; j++) {
        *(__half2*)(o0 + 8 * j) = __floats2half2_rn(oacc[j][0] * inv0, oacc[j][1] * inv0);
        *(__half2*)(o1 + 8 * j) = __floats2half2_rn(oacc[j][2] * inv1, oacc[j][3] * inv1);
    }
}

// ---------------- fused per-batch maxabs + normalize ----------------
__global__ void norm_kernel(const float* __restrict__ phi, float* __restrict__ out) {
    int b = blockIdx.x;
    int n = threadIdx.x; // 256
    __shared__ float sm[256][8];
    float v[8];
    #pragma unroll
    for (int j = 0; j < 8; j++) {
        v[j] = phi[((size_t)b * NN + n) * MODEN + j];
        sm[n][j] = fabsf(v[j]);
    }
    __syncthreads();
    for (int s = 128; s > 0; s >>= 1) {
        if (n < s) {
            #pragma unroll
            for (int j = 0; j < 8; j++) sm[n][j] = fmaxf(sm[n][j], sm[n + s][j]);
        }
        __syncthreads();
    }
    #pragma unroll
    for (int j = 0; j < 8; j++)
        out[((size_t)b * NN + n) * MODEN + j] = v[j] / sm[0][j];
}

// ---------------- launch ----------------
extern "C" void kernel_launch(void* const* d_in, const int* in_sizes, int n_in,
                              void* d_out, int out_size) {
    (void)in_sizes; (void)n_in; (void)out_size;
    const float* acc_Y      = (const float*)d_in[0];
    const float* proj_in_w  = (const float*)d_in[2];
    const float* proj_in_b  = (const float*)d_in[3];
    const float* attn_in_w  = (const float*)d_in[4];
    const float* attn_in_b  = (const float*)d_in[5];
    const float* attn_out_w = (const float*)d_in[6];
    const float* attn_out_b = (const float*)d_in[7];
    const float* ln1_g      = (const float*)d_in[8];
    const float* ln1_b      = (const float*)d_in[9];
    const float* ff1_w      = (const float*)d_in[10];
    const float* ff1_b      = (const float*)d_in[11];
    const float* ff2_w      = (const float*)d_in[12];
    const float* ff2_b      = (const float*)d_in[13];
    const float* ln2_g      = (const float*)d_in[14];
    const float* ln2_b      = (const float*)d_in[15];
    const float* proj_out_w = (const float*)d_in[16];
    const float* proj_out_b = (const float*)d_in[17];
    const float* mlp1_w     = (const float*)d_in[18];
    const float* mlp1_b     = (const float*)d_in[19];
    const float* mlp2_w     = (const float*)d_in[20];
    const float* mlp2_b     = (const float*)d_in[21];
    const float* mlp3_w     = (const float*)d_in[22];
    const float* mlp3_b     = (const float*)d_in[23];
    float* out = (float*)d_out;

    float  *pX, *pX2, *pPHI;
    __half *pXh, *pX2h, *pQKVh, *pCTXh, *pTMPh, *pWh;
    cudaGetSymbolAddress((void**)&pX,    g_X);
    cudaGetSymbolAddress((void**)&pXh,   g_Xh);
    cudaGetSymbolAddress((void**)&pX2,   g_X2);
    cudaGetSymbolAddress((void**)&pX2h,  g_X2h);
    cudaGetSymbolAddress((void**)&pQKVh, g_QKVh);
    cudaGetSymbolAddress((void**)&pCTXh, g_CTXh);
    cudaGetSymbolAddress((void**)&pTMPh, g_TMPh);
    cudaGetSymbolAddress((void**)&pPHI,  g_PHI);
    cudaGetSymbolAddress((void**)&pWh,   g_Wh);

    // weight pre-conversion (once per replay)
    convw_kernel<<<W_TOTAL / 256, 256>>>(attn_in_w, attn_out_w, ff1_w, ff2_w, mlp1_w, mlp2_w, pWh);

    // ===== q path =====
    proj_in_kernel<<<MQ, 128>>>(acc_Y, proj_in_w, proj_in_b, pX, pXh);
    hgemm_kernel<0,1><<<dim3(6, MQ / 128), 256>>>(pXh, pWh + W_ATTNIN, attn_in_b, pQKVh, MQ, 384, 128);
    attn_mma_kernel<<<dim3(LL / 128, HH, BB), 256>>>(pQKVh, pCTXh);
    hgemm_ln_kernel<0><<<MQ / 128, 256>>>(pCTXh, pWh + W_ATTNOUT, attn_out_b, pX, ln1_g, ln1_b,
                                          pX2, pX2h, nullptr, nullptr, nullptr, MQ, 128);
    hgemm_kernel<1,1><<<dim3(4, MQ / 128), 256>>>(pX2h, pWh + W_FF1, ff1_b, pTMPh, MQ, 256, 128);
    hgemm_ln_kernel<1><<<MQ / 128, 256>>>(pTMPh, pWh + W_FF2, ff2_b, pX2, ln2_g, ln2_b,
                                          nullptr, nullptr, proj_out_w, proj_out_b, out, MQ, 256);

    // ===== phi path (fused) =====
    phi_fused_kernel<<<MP / 128, 256>>>(acc_Y, pWh + W_MLP1, mlp1_b, pWh + W_MLP2, mlp2_b,
                                        mlp3_w, mlp3_b, pPHI);
    norm_kernel<<<BB, 256>>>(pPHI, out + MQ * MODEN);
}

// round 14
// speedup vs baseline: 4.4406x; 1.0472x over previous
#include <cuda_runtime.h>
#include <cuda_fp16.h>
#include <cuda_bf16.h>
#include <math.h>
#include <stdint.h>

// ---------------- problem constants ----------------
#define BB    32
#define NN    256
#define LL    1024
#define DIMD  128
#define MODEN 8
#define HH    4
#define DHD   32
#define FFD   256
#define MQ    (BB*LL)    // 32768 rows, q path
#define MP    (BB*NN)    // 8192 rows, phi path
// ATTN_SCALE * log2(e): scores leave the S-MMA in log2 domain
#define SCALE_LOG2E 0.2550052662477581f

// half-weight buffer offsets
#define W_ATTNIN  0                      // 384*128 = 49152 (q-part pre-scaled)
#define W_ATTNOUT 49152                  // 128*128 = 16384
#define W_FF1     65536                  // 256*128 = 32768
#define W_FF2     98304                  // 128*256 = 32768
#define W_MLP1    131072                 // 128*1024 = 131072
#define W_MLP2    262144                 // 128*128 = 16384
#define W_TOTAL   278528

// ---------------- scratch (device globals; no allocation allowed) ----------------
__device__ float  g_X   [MQ * DIMD];
__device__ __half g_Xh  [MQ * DIMD];
__device__ float  g_X2  [MQ * DIMD];
__device__ __half g_X2h [MQ * DIMD];
__device__ __half g_QKVh[MQ * 3 * DIMD];
__device__ __half g_CTXh[MQ * DIMD];
__device__ __half g_TMPh[MQ * FFD];
__device__ float  g_PHI [MP * MODEN];
__device__ __half g_Wh  [W_TOTAL];
__device__ float  g_ABb [3 * DIMD];      // attn_in bias, q-part pre-scaled

// ---------------- helpers ----------------
__device__ __forceinline__ uint32_t smem_u32(const void* p) {
    return (uint32_t)__cvta_generic_to_shared(p);
}

__device__ __forceinline__ uint32_t f2h2(float a, float b) {
    __half2 h = __floats2half2_rn(a, b);
    return *reinterpret_cast<uint32_t*>(&h);
}

__device__ __forceinline__ float ex2f(float x) {
    float r;
    asm("ex2.approx.f32 %0, %1;" : "=f"(r) : "f"(x));
    return r;
}

#define LDSM4(r0,r1,r2,r3,addr) \
    asm volatile("ldmatrix.sync.aligned.m8n8.x4.shared.b16 {%0,%1,%2,%3},[%4];" \
                 : "=r"(r0),"=r"(r1),"=r"(r2),"=r"(r3) : "r"(addr))
#define LDSM4T(r0,r1,r2,r3,addr) \
    asm volatile("ldmatrix.sync.aligned.m8n8.x4.trans.shared.b16 {%0,%1,%2,%3},[%4];" \
                 : "=r"(r0),"=r"(r1),"=r"(r2),"=r"(r3) : "r"(addr))
#define MMA16816(c,a0,a1,a2,a3,b0,b1) \
    asm volatile("mma.sync.aligned.m16n8k16.row.col.f32.f16.f16.f32 " \
                 "{%0,%1,%2,%3},{%4,%5,%6,%7},{%8,%9},{%0,%1,%2,%3};" \
                 : "+f"(c[0]),"+f"(c[1]),"+f"(c[2]),"+f"(c[3]) \
                 : "r"(a0),"r"(a1),"r"(a2),"r"(a3),"r"(b0),"r"(b1))

// ---------------- one-shot weight conversion fp32 -> fp16 (q-part scaled) ----------------
__global__ void convw_kernel(const float* __restrict__ aw, const float* __restrict__ ow,
                             const float* __restrict__ f1, const float* __restrict__ f2,
                             const float* __restrict__ m1, const float* __restrict__ m2,
                             __half* __restrict__ dst) {
    int i = blockIdx.x * 256 + threadIdx.x;   // 0 .. W_TOTAL-1
    float v;
    if      (i < W_ATTNOUT) { v = aw[i]; if (i < DIMD * DIMD) v *= SCALE_LOG2E; }
    else if (i < W_FF1)     v = ow[i - W_ATTNOUT];
    else if (i < W_FF2)     v = f1[i - W_FF1];
    else if (i < W_MLP1)    v = f2[i - W_FF2];
    else if (i < W_MLP2)    v = m1[i - W_MLP1];
    else                    v = m2[i - W_MLP2];
    dst[i] = __float2half(v);
}

__global__ void biasq_kernel(const float* __restrict__ b, float* __restrict__ dst) {
    int i = threadIdx.x + blockIdx.x * 192;   // 2 blocks x 192 = 384
    if (i < 3 * DIMD) dst[i] = (i < DIMD) ? b[i] * SCALE_LOG2E : b[i];
}

// ---------------- proj_in: writes fp32 + fp16 ----------------
__global__ void proj_in_kernel(const float* __restrict__ Y,
                               const float* __restrict__ w,
                               const float* __restrict__ bias,
                               float* __restrict__ X,
                               __half* __restrict__ Xh) {
    int r = blockIdx.x;
    int b = r >> 10;
    int l = r & 1023;
    int t = threadIdx.x;              // 128
    __shared__ float xs[7];
    if (t < 7) xs[t] = Y[((size_t)b * NN + 2 + t) * LL + l];
    __syncthreads();
    float acc = bias[t];
    #pragma unroll
    for (int j = 0; j < 7; j++) acc += xs[j] * w[t * 7 + j];
    X[(size_t)r * DIMD + t]  = acc;
    Xh[(size_t)r * DIMD + t] = __float2half(acc);
}

// ---------------- fp16 tensor-core GEMM (N-tile 64), half A + half W ----------------
template<int ACT, int CHALF>
__global__ __launch_bounds__(256) void hgemm_kernel(const __half* __restrict__ A,
                                                    const __half* __restrict__ W,
                                                    const float* __restrict__ bias,
                                                    void* __restrict__ Cv,
                                                    int M, int N, int K) {
    __shared__ __half As[128][72];
    __shared__ __half Bs[64][72];
    int tid = threadIdx.x;
    int w = tid >> 5, lane = tid & 31;
    int bm = blockIdx.y * 128;
    int bn = blockIdx.x * 64;

    float acc[8][4];
    #pragma unroll
    for (int j = 0; j < 8; j++)
        #pragma unroll
        for (int c = 0; c < 4; c++) acc[j][c] = 0.f;

    for (int kt = 0; kt < K; kt += 64) {
        #pragma unroll
        for (int i = 0; i < 4; i++) {
            int idx = tid + i * 256;
            int row = idx >> 3;
            int c8  = (idx & 7) * 8;
            *(uint4*)&As[row][c8] = *(const uint4*)&A[(size_t)(bm + row) * K + kt + c8];
        }
        #pragma unroll
        for (int i = 0; i < 2; i++) {
            int idx = tid + i * 256;
            int row = idx >> 3;
            int c8  = (idx & 7) * 8;
            *(uint4*)&Bs[row][c8] = *(const uint4*)&W[(size_t)(bn + row) * K + kt + c8];
        }
        __syncthreads();

        #pragma unroll
        for (int ks2 = 0; ks2 < 2; ks2++) {
            uint32_t af[2][4];
            #pragma unroll
            for (int s = 0; s < 2; s++) {
                int row = 16 * w + (lane & 15);
                int col = ks2 * 32 + s * 16 + (lane >> 4) * 8;
                LDSM4(af[s][0], af[s][1], af[s][2], af[s][3], smem_u32(&As[row][col]));
            }
            #pragma unroll
            for (int j = 0; j < 8; j++) {
                uint32_t bf[4];
                uint32_t addr = smem_u32(&Bs[8 * j + (lane & 7)][ks2 * 32 + (lane >> 3) * 8]);
                LDSM4(bf[0], bf[1], bf[2], bf[3], addr);
                MMA16816(acc[j], af[0][0], af[0][1], af[0][2], af[0][3], bf[0], bf[1]);
                MMA16816(acc[j], af[1][0], af[1][1], af[1][2], af[1][3], bf[2], bf[3]);
            }
        }
        __syncthreads();
    }

    int row0 = bm + 16 * w + (lane >> 2);
    int row1 = row0 + 8;
    #pragma unroll
    for (int j = 0; j < 8; j++) {
        int col = bn + 8 * j + 2 * (lane & 3);
        float b0 = bias[col], b1 = bias[col + 1];
        float v0 = acc[j][0] + b0, v1 = acc[j][1] + b1;
        float v2 = acc[j][2] + b0, v3 = acc[j][3] + b1;
        if (ACT == 1) { v0 = fmaxf(v0, 0.f); v1 = fmaxf(v1, 0.f); v2 = fmaxf(v2, 0.f); v3 = fmaxf(v3, 0.f); }
        if (CHALF) {
            __half* C = (__half*)Cv;
            *(__half2*)&C[(size_t)row0 * N + col] = __floats2half2_rn(v0, v1);
            *(__half2*)&C[(size_t)row1 * N + col] = __floats2half2_rn(v2, v3);
        } else {
            float* C = (float*)Cv;
            *(float2*)&C[(size_t)row0 * N + col] = make_float2(v0, v1);
            *(float2*)&C[(size_t)row1 * N + col] = make_float2(v2, v3);
        }
    }
}

// ---------------- fused GEMM(N=128) + residual + LayerNorm [+ q projection] ----------------
template<int QPROJ>
__global__ __launch_bounds__(256) void hgemm_ln_kernel(const __half* __restrict__ A,
                                                       const __half* __restrict__ W,
                                                       const float* __restrict__ bias,
                                                       const float* __restrict__ res,
                                                       const float* __restrict__ lng,
                                                       const float* __restrict__ lnb,
                                                       float* __restrict__ Xout,
                                                       __half* __restrict__ Xhout,
                                                       const float* __restrict__ qw,
                                                       const float* __restrict__ qb,
                                                       float* __restrict__ qout,
                                                       int M, int K) {
    __shared__ __half As[128][72];
    __shared__ __half Bs[128][72];
    __shared__ float  qws[8][128];
    int tid = threadIdx.x;
    int w = tid >> 5, lane = tid & 31;
    int bm = blockIdx.x * 128;

    if (QPROJ) {
        ((float4*)qws)[tid] = ((const float4*)qw)[tid];
    }

    float acc[16][4];
    #pragma unroll
    for (int j = 0; j < 16; j++)
        #pragma unroll
        for (int c = 0; c < 4; c++) acc[j][c] = 0.f;

    for (int kt = 0; kt < K; kt += 64) {
        #pragma unroll
        for (int i = 0; i < 4; i++) {
            int idx = tid + i * 256;
            int row = idx >> 3;
            int c8  = (idx & 7) * 8;
            *(uint4*)&As[row][c8] = *(const uint4*)&A[(size_t)(bm + row) * K + kt + c8];
        }
        #pragma unroll
        for (int i = 0; i < 4; i++) {
            int idx = tid + i * 256;
            int row = idx >> 3;
            int c8  = (idx & 7) * 8;
            *(uint4*)&Bs[row][c8] = *(const uint4*)&W[(size_t)row * K + kt + c8];
        }
        __syncthreads();

        #pragma unroll
        for (int ks2 = 0; ks2 < 2; ks2++) {
            uint32_t af[2][4];
            #pragma unroll
            for (int s = 0; s < 2; s++) {
                int row = 16 * w + (lane & 15);
                int col = ks2 * 32 + s * 16 + (lane >> 4) * 8;
                LDSM4(af[s][0], af[s][1], af[s][2], af[s][3], smem_u32(&As[row][col]));
            }
            #pragma unroll
            for (int j = 0; j < 16; j++) {
                uint32_t bf[4];
                uint32_t addr = smem_u32(&Bs[8 * j + (lane & 7)][ks2 * 32 + (lane >> 3) * 8]);
                LDSM4(bf[0], bf[1], bf[2], bf[3], addr);
                MMA16816(acc[j], af[0][0], af[0][1], af[0][2], af[0][3], bf[0], bf[1]);
                MMA16816(acc[j], af[1][0], af[1][1], af[1][2], af[1][3], bf[2], bf[3]);
            }
        }
        __syncthreads();
    }

    int grow0 = bm + 16 * w + (lane >> 2);
    int grow1 = grow0 + 8;
    float s0 = 0.f, q0 = 0.f, s1 = 0.f, q1 = 0.f;
    #pragma unroll
    for (int j = 0; j < 16; j++) {
        int col = 8 * j + 2 * (lane & 3);
        float2 r0 = *(const float2*)&res[(size_t)grow0 * DIMD + col];
        float2 r1 = *(const float2*)&res[(size_t)grow1 * DIMD + col];
        float b0 = bias[col], b1 = bias[col + 1];
        acc[j][0] += b0 + r0.x;  acc[j][1] += b1 + r0.y;
        acc[j][2] += b0 + r1.x;  acc[j][3] += b1 + r1.y;
        s0 += acc[j][0] + acc[j][1];
        q0 += acc[j][0] * acc[j][0] + acc[j][1] * acc[j][1];
        s1 += acc[j][2] + acc[j][3];
        q1 += acc[j][2] * acc[j][2] + acc[j][3] * acc[j][3];
    }
    #pragma unroll
    for (int o = 1; o <= 2; o <<= 1) {
        s0 += __shfl_xor_sync(0xffffffffu, s0, o);
        q0 += __shfl_xor_sync(0xffffffffu, q0, o);
        s1 += __shfl_xor_sync(0xffffffffu, s1, o);
        q1 += __shfl_xor_sync(0xffffffffu, q1, o);
    }
    float mean0 = s0 * (1.f / 128.f), mean1 = s1 * (1.f / 128.f);
    float rs0 = rsqrtf(q0 * (1.f / 128.f) - mean0 * mean0 + 1e-5f);
    float rs1 = rsqrtf(q1 * (1.f / 128.f) - mean1 * mean1 + 1e-5f);

    if (!QPROJ) {
        #pragma unroll
        for (int j = 0; j < 16; j++) {
            int col = 8 * j + 2 * (lane & 3);
            float g0 = lng[col], g1 = lng[col + 1];
            float bb0 = lnb[col], bb1 = lnb[col + 1];
            float v0 = (acc[j][0] - mean0) * rs0 * g0 + bb0;
            float v1 = (acc[j][1] - mean0) * rs0 * g1 + bb1;
            float v2 = (acc[j][2] - mean1) * rs1 * g0 + bb0;
            float v3 = (acc[j][3] - mean1) * rs1 * g1 + bb1;
            *(float2*)&Xout[(size_t)grow0 * DIMD + col] = make_float2(v0, v1);
            *(float2*)&Xout[(size_t)grow1 * DIMD + col] = make_float2(v2, v3);
            *(__half2*)&Xhout[(size_t)grow0 * DIMD + col] = __floats2half2_rn(v0, v1);
            *(__half2*)&Xhout[(size_t)grow1 * DIMD + col] = __floats2half2_rn(v2, v3);
        }
    } else {
        float p0[8], p1[8];
        #pragma unroll
        for (int o = 0; o < 8; o++) { p0[o] = 0.f; p1[o] = 0.f; }
        #pragma unroll
        for (int j = 0; j < 16; j++) {
            int col = 8 * j + 2 * (lane & 3);
            float g0 = lng[col], g1 = lng[col + 1];
            float bb0 = lnb[col], bb1 = lnb[col + 1];
            float v0 = (acc[j][0] - mean0) * rs0 * g0 + bb0;
            float v1 = (acc[j][1] - mean0) * rs0 * g1 + bb1;
            float v2 = (acc[j][2] - mean1) * rs1 * g0 + bb0;
            float v3 = (acc[j][3] - mean1) * rs1 * g1 + bb1;
            #pragma unroll
            for (int o = 0; o < 8; o++) {
                p0[o] += v0 * qws[o][col] + v1 * qws[o][col + 1];
                p1[o] += v2 * qws[o][col] + v3 * qws[o][col + 1];
            }
        }
        #pragma unroll
        for (int o = 0; o < 8; o++) {
            #pragma unroll
            for (int m = 1; m <= 2; m <<= 1) {
                p0[o] += __shfl_xor_sync(0xffffffffu, p0[o], m);
                p1[o] += __shfl_xor_sync(0xffffffffu, p1[o], m);
            }
        }
        int k2 = lane & 3;
        float qb0 = qb[2 * k2], qb1 = qb[2 * k2 + 1];
        *(float2*)&qout[(size_t)grow0 * MODEN + 2 * k2] = make_float2(p0[2 * k2] + qb0, p0[2 * k2 + 1] + qb1);
        *(float2*)&qout[(size_t)grow1 * MODEN + 2 * k2] = make_float2(p1[2 * k2] + qb0, p1[2 * k2 + 1] + qb1);
    }
}

// ---------------- fused phi MLP ----------------
__global__ __launch_bounds__(256) void phi_fused_kernel(const float* __restrict__ Y,
                                                        const __half* __restrict__ W1h,
                                                        const float* __restrict__ b1,
                                                        const __half* __restrict__ W2h,
                                                        const float* __restrict__ b2,
                                                        const float* __restrict__ W3,
                                                        const float* __restrict__ b3,
                                                        float* __restrict__ PHI) {
    __shared__ __half As[128][72];
    __shared__ __half Bs[128][72];
    __shared__ float  w3s[8][128];
    int tid = threadIdx.x;
    int w = tid >> 5, lane = tid & 31;
    int bm = blockIdx.x * 128;

    ((float4*)w3s)[tid] = ((const float4*)W3)[tid];

    float acc[16][4];
    #pragma unroll
    for (int j = 0; j < 16; j++)
        #pragma unroll
        for (int c = 0; c < 4; c++) acc[j][c] = 0.f;

    for (int kt = 0; kt < 1024; kt += 64) {
        #pragma unroll
        for (int i = 0; i < 8; i++) {
            int idx = tid + i * 256;
            int row = idx >> 4;
            int c4  = (idx & 15) * 4;
            float4 f = *(const float4*)&Y[(size_t)(bm + row) * 1024 + kt + c4];
            __half2* d = (__half2*)&As[row][c4];
            d[0] = __floats2half2_rn(f.x, f.y);
            d[1] = __floats2half2_rn(f.z, f.w);
        }
        #pragma unroll
        for (int i = 0; i < 4; i++) {
            int idx = tid + i * 256;
            int row = idx >> 3;
            int c8  = (idx & 7) * 8;
            *(uint4*)&Bs[row][c8] = *(const uint4*)&W1h[(size_t)row * 1024 + kt + c8];
        }
        __syncthreads();
        #pragma unroll
        for (int ks2 = 0; ks2 < 2; ks2++) {
            uint32_t af[2][4];
            #pragma unroll
            for (int s = 0; s < 2; s++) {
                int row = 16 * w + (lane & 15);
                int col = ks2 * 32 + s * 16 + (lane >> 4) * 8;
                LDSM4(af[s][0], af[s][1], af[s][2], af[s][3], smem_u32(&As[row][col]));
            }
            #pragma unroll
            for (int j = 0; j < 16; j++) {
                uint32_t bf[4];
                uint32_t addr = smem_u32(&Bs[8 * j + (lane & 7)][ks2 * 32 + (lane >> 3) * 8]);
                LDSM4(bf[0], bf[1], bf[2], bf[3], addr);
                MMA16816(acc[j], af[0][0], af[0][1], af[0][2], af[0][3], bf[0], bf[1]);
                MMA16816(acc[j], af[1][0], af[1][1], af[1][2], af[1][3], bf[2], bf[3]);
            }
        }
        __syncthreads();
    }

    uint32_t af2[8][4];
    #pragma unroll
    for (int j = 0; j < 16; j++) {
        int col = 8 * j + 2 * (lane & 3);
        float b0 = b1[col], bb1 = b1[col + 1];
        acc[j][0] = tanhf(acc[j][0] + b0);
        acc[j][1] = tanhf(acc[j][1] + bb1);
        acc[j][2] = tanhf(acc[j][2] + b0);
        acc[j][3] = tanhf(acc[j][3] + bb1);
    }
    #pragma unroll
    for (int s = 0; s < 8; s++) {
        af2[s][0] = f2h2(acc[2 * s][0],     acc[2 * s][1]);
        af2[s][1] = f2h2(acc[2 * s][2],     acc[2 * s][3]);
        af2[s][2] = f2h2(acc[2 * s + 1][0], acc[2 * s + 1][1]);
        af2[s][3] = f2h2(acc[2 * s + 1][2], acc[2 * s + 1][3]);
    }

    #pragma unroll
    for (int i = 0; i < 4; i++) {
        int idx = tid + i * 256;
        int row = idx >> 3;
        int c8  = (idx & 7) * 8;
        *(uint4*)&As[row][c8] = *(const uint4*)&W2h[(size_t)row * 128 + c8];
        *(uint4*)&Bs[row][c8] = *(const uint4*)&W2h[(size_t)row * 128 + 64 + c8];
    }
    __syncthreads();

    #pragma unroll
    for (int layer = 0; layer < 2; layer++) {
        #pragma unroll
        for (int j = 0; j < 16; j++)
            #pragma unroll
            for (int c = 0; c < 4; c++) acc[j][c] = 0.f;
        #pragma unroll
        for (int sub = 0; sub < 4; sub++) {
            int co = (sub & 1) * 32;
            #pragma unroll
            for (int j = 0; j < 16; j++) {
                uint32_t bf[4];
                uint32_t addr = (sub < 2)
                    ? smem_u32(&As[8 * j + (lane & 7)][co + (lane >> 3) * 8])
                    : smem_u32(&Bs[8 * j + (lane & 7)][co + (lane >> 3) * 8]);
                LDSM4(bf[0], bf[1], bf[2], bf[3], addr);
                MMA16816(acc[j], af2[2 * sub][0], af2[2 * sub][1], af2[2 * sub][2], af2[2 * sub][3], bf[0], bf[1]);
                MMA16816(acc[j], af2[2 * sub + 1][0], af2[2 * sub + 1][1], af2[2 * sub + 1][2], af2[2 * sub + 1][3], bf[2], bf[3]);
            }
        }
        #pragma unroll
        for (int j = 0; j < 16; j++) {
            int col = 8 * j + 2 * (lane & 3);
            float b0 = b2[col], bb1 = b2[col + 1];
            acc[j][0] = tanhf(acc[j][0] + b0);
            acc[j][1] = tanhf(acc[j][1] + bb1);
            acc[j][2] = tanhf(acc[j][2] + b0);
            acc[j][3] = tanhf(acc[j][3] + bb1);
        }
        if (layer == 0) {
            #pragma unroll
            for (int s = 0; s < 8; s++) {
                af2[s][0] = f2h2(acc[2 * s][0],     acc[2 * s][1]);
                af2[s][1] = f2h2(acc[2 * s][2],     acc[2 * s][3]);
                af2[s][2] = f2h2(acc[2 * s + 1][0], acc[2 * s + 1][1]);
                af2[s][3] = f2h2(acc[2 * s + 1][2], acc[2 * s + 1][3]);
            }
        }
    }

    float p0[8], p1[8];
    #pragma unroll
    for (int o = 0; o < 8; o++) { p0[o] = 0.f; p1[o] = 0.f; }
    #pragma unroll
    for (int j = 0; j < 16; j++) {
        int col = 8 * j + 2 * (lane & 3);
        #pragma unroll
        for (int o = 0; o < 8; o++) {
            p0[o] += acc[j][0] * w3s[o][col] + acc[j][1] * w3s[o][col + 1];
            p1[o] += acc[j][2] * w3s[o][col] + acc[j][3] * w3s[o][col + 1];
        }
    }
    #pragma unroll
    for (int o = 0; o < 8; o++) {
        #pragma unroll
        for (int m = 1; m <= 2; m <<= 1) {
            p0[o] += __shfl_xor_sync(0xffffffffu, p0[o], m);
            p1[o] += __shfl_xor_sync(0xffffffffu, p1[o], m);
        }
    }
    int grow0 = bm + 16 * w + (lane >> 2);
    int grow1 = grow0 + 8;
    int k2 = lane & 3;
    float b30 = b3[2 * k2], b31 = b3[2 * k2 + 1];
    *(float2*)&PHI[(size_t)grow0 * MODEN + 2 * k2] = make_float2(p0[2 * k2] + b30, p0[2 * k2 + 1] + b31);
    *(float2*)&PHI[(size_t)grow1 * MODEN + 2 * k2] = make_float2(p1[2 * k2] + b30, p1[2 * k2 + 1] + b31);
}

// ---------------- fp16 flash attention, 128-key tiles, log2-domain softmax ----------------
// Q pre-scaled by ATTN_SCALE*log2e (folded into Wq/bq). grid (L/128, H, B), 256 thr.
__global__ __launch_bounds__(256) void attn_mma_kernel(const __half* __restrict__ QKV,
                                                       __half* __restrict__ CTX) {
    int h = blockIdx.y;
    int b = blockIdx.z;
    int qbase = blockIdx.x * 128;
    int t = threadIdx.x;
    int w = t >> 5, lane = t & 31;

    __shared__ __half Qs[128][40];
    __shared__ __half Ks[128][40];
    __shared__ __half Vs[128][40];

    const __half* base = QKV + (size_t)b * (LL * 384);

    #pragma unroll
    for (int i = 0; i < 2; i++) {
        int idx = t + i * 256;
        int row = idx >> 2;
        int c8  = (idx & 3) * 8;
        *(uint4*)&Qs[row][c8] =
            *(const uint4*)(base + (size_t)(qbase + row) * 384 + h * 32 + c8);
    }

    // K/V tile loads: thread tt covers one full row (4 uint4 = 32 halves)
    int tt = t & 127;
    int koff = (t < 128) ? 128 : 256;
    uint4 pf[4];
    {
        const uint4* s = (const uint4*)(base + (size_t)tt * 384 + koff + h * 32);
        pf[0] = s[0]; pf[1] = s[1]; pf[2] = s[2]; pf[3] = s[3];
    }
    __syncthreads();

    uint32_t qa[2][4];
    {
        int qr = w * 16;
        #pragma unroll
        for (int s = 0; s < 2; s++) {
            int row = qr + (lane & 15);
            int col = s * 16 + (lane >> 4) * 8;
            LDSM4(qa[s][0], qa[s][1], qa[s][2], qa[s][3], smem_u32(&Qs[row][col]));
        }
    }

    float oacc[4][4];
    #pragma unroll
    for (int j = 0; j < 4; j++)
        #pragma unroll
        for (int c = 0; c < 4; c++) oacc[j][c] = 0.f;
    float mrun0 = -1e30f, mrun1 = -1e30f, l0 = 0.f, l1 = 0.f;

    for (int kt = 0; kt < 8; kt++) {
        {
            uint4* d = (uint4*)&((t < 128) ? Ks : Vs)[tt][0];
            d[0] = pf[0]; d[1] = pf[1]; d[2] = pf[2]; d[3] = pf[3];
        }
        __syncthreads();
        if (kt < 7) {
            const uint4* s = (const uint4*)(base + (size_t)((kt + 1) * 128 + tt) * 384 + koff + h * 32);
            pf[0] = s[0]; pf[1] = s[1]; pf[2] = s[2]; pf[3] = s[3];
        }

        // ---- S = Q K^T (scores already in log2 domain) ----
        float sacc[16][4];
        #pragma unroll
        for (int j = 0; j < 16; j++)
            #pragma unroll
            for (int c = 0; c < 4; c++) sacc[j][c] = 0.f;

        #pragma unroll
        for (int j = 0; j < 16; j++) {
            uint32_t kb[4];
            uint32_t addr = smem_u32(&Ks[8 * j + (lane & 7)][(lane >> 3) * 8]);
            LDSM4(kb[0], kb[1], kb[2], kb[3], addr);
            MMA16816(sacc[j], qa[0][0], qa[0][1], qa[0][2], qa[0][3], kb[0], kb[1]);
            MMA16816(sacc[j], qa[1][0], qa[1][1], qa[1][2], qa[1][3], kb[2], kb[3]);
        }

        // ---- online softmax in base-2 ----
        float mx0 = -1e30f, mx1 = -1e30f;
        #pragma unroll
        for (int j = 0; j < 16; j++) {
            mx0 = fmaxf(mx0, fmaxf(sacc[j][0], sacc[j][1]));
            mx1 = fmaxf(mx1, fmaxf(sacc[j][2], sacc[j][3]));
        }
        #pragma unroll
        for (int o = 1; o <= 2; o <<= 1) {
            mx0 = fmaxf(mx0, __shfl_xor_sync(0xffffffffu, mx0, o));
            mx1 = fmaxf(mx1, __shfl_xor_sync(0xffffffffu, mx1, o));
        }
        float nm0 = fmaxf(mrun0, mx0), nm1 = fmaxf(mrun1, mx1);
        float al0 = ex2f(mrun0 - nm0), al1 = ex2f(mrun1 - nm1);
        mrun0 = nm0; mrun1 = nm1;

        float rs0 = 0.f, rs1 = 0.f;
        #pragma unroll
        for (int j = 0; j < 16; j++) {
            sacc[j][0] = ex2f(sacc[j][0] - nm0); rs0 += sacc[j][0];
            sacc[j][1] = ex2f(sacc[j][1] - nm0); rs0 += sacc[j][1];
            sacc[j][2] = ex2f(sacc[j][2] - nm1); rs1 += sacc[j][2];
            sacc[j][3] = ex2f(sacc[j][3] - nm1); rs1 += sacc[j][3];
        }
        #pragma unroll
        for (int o = 1; o <= 2; o <<= 1) {
            rs0 += __shfl_xor_sync(0xffffffffu, rs0, o);
            rs1 += __shfl_xor_sync(0xffffffffu, rs1, o);
        }
        l0 = l0 * al0 + rs0;
        l1 = l1 * al1 + rs1;
        #pragma unroll
        for (int j = 0; j < 4; j++) {
            oacc[j][0] *= al0; oacc[j][1] *= al0;
            oacc[j][2] *= al1; oacc[j][3] *= al1;
        }

        // ---- O += P V : 8 k-chunks of 16 keys ----
        #pragma unroll
        for (int s = 0; s < 8; s++) {
            uint32_t pa0 = f2h2(sacc[2 * s][0], sacc[2 * s][1]);
            uint32_t pa1 = f2h2(sacc[2 * s][2], sacc[2 * s][3]);
            uint32_t pa2 = f2h2(sacc[2 * s + 1][0], sacc[2 * s + 1][1]);
            uint32_t pa3 = f2h2(sacc[2 * s + 1][2], sacc[2 * s + 1][3]);
            #pragma unroll
            for (int jj = 0; jj < 2; jj++) {
                uint32_t vb[4];
                uint32_t addr = smem_u32(&Vs[16 * s + (lane & 15)][8 * (2 * jj + (lane >> 4))]);
                LDSM4T(vb[0], vb[1], vb[2], vb[3], addr);
                MMA16816(oacc[2 * jj],     pa0, pa1, pa2, pa3, vb[0], vb[1]);
                MMA16816(oacc[2 * jj + 1], pa0, pa1, pa2, pa3, vb[2], vb[3]);
            }
        }
        __syncthreads();
    }

    float inv0 = 1.f / l0, inv1 = 1.f / l1;
    int r0 = qbase + w * 16 + (lane >> 2);
    __half* o0 = CTX + ((size_t)(b * LL + r0)) * DIMD + h * 32 + 2 * (lane & 3);
    __half* o1 = o0 + 8 * DIMD;
    #pragma unroll
    for (int j = 0; j < 4; j++) {
        *(__half2*)(o0 + 8 * j) = __floats2half2_rn(oacc[j][0] * inv0, oacc[j][1] * inv0);
        *(__half2*)(o1 + 8 * j) = __floats2half2_rn(oacc[j][2] * inv1, oacc[j][3] * inv1);
    }
}

// ---------------- fused per-batch maxabs + normalize ----------------
__global__ void norm_kernel(const float* __restrict__ phi, float* __restrict__ out) {
    int b = blockIdx.x;
    int n = threadIdx.x; // 256
    __shared__ float sm[256][8];
    float v[8];
    #pragma unroll
    for (int j = 0; j < 8; j++) {
        v[j] = phi[((size_t)b * NN + n) * MODEN + j];
        sm[n][j] = fabsf(v[j]);
    }
    __syncthreads();
    for (int s = 128; s > 0; s >>= 1) {
        if (n < s) {
            #pragma unroll
            for (int j = 0; j < 8; j++) sm[n][j] = fmaxf(sm[n][j], sm[n + s][j]);
        }
        __syncthreads();
    }
    #pragma unroll
    for (int j = 0; j < 8; j++)
        out[((size_t)b * NN + n) * MODEN + j] = v[j] / sm[0][j];
}

// ---------------- launch ----------------
extern "C" void kernel_launch(void* const* d_in, const int* in_sizes, int n_in,
                              void* d_out, int out_size) {
    (void)in_sizes; (void)n_in; (void)out_size;
    const float* acc_Y      = (const float*)d_in[0];
    const float* proj_in_w  = (const float*)d_in[2];
    const float* proj_in_b  = (const float*)d_in[3];
    const float* attn_in_w  = (const float*)d_in[4];
    const float* attn_in_b  = (const float*)d_in[5];
    const float* attn_out_w = (const float*)d_in[6];
    const float* attn_out_b = (const float*)d_in[7];
    const float* ln1_g      = (const float*)d_in[8];
    const float* ln1_b      = (const float*)d_in[9];
    const float* ff1_w      = (const float*)d_in[10];
    const float* ff1_b      = (const float*)d_in[11];
    const float* ff2_w      = (const float*)d_in[12];
    const float* ff2_b      = (const float*)d_in[13];
    const float* ln2_g      = (const float*)d_in[14];
    const float* ln2_b      = (const float*)d_in[15];
    const float* proj_out_w = (const float*)d_in[16];
    const float* proj_out_b = (const float*)d_in[17];
    const float* mlp1_w     = (const float*)d_in[18];
    const float* mlp1_b     = (const float*)d_in[19];
    const float* mlp2_w     = (const float*)d_in[20];
    const float* mlp2_b     = (const float*)d_in[21];
    const float* mlp3_w     = (const float*)d_in[22];
    const float* mlp3_b     = (const float*)d_in[23];
    float* out = (float*)d_out;

    float  *pX, *pX2, *pPHI, *pABb;
    __half *pXh, *pX2h, *pQKVh, *pCTXh, *pTMPh, *pWh;
    cudaGetSymbolAddress((void**)&pX,    g_X);
    cudaGetSymbolAddress((void**)&pXh,   g_Xh);
    cudaGetSymbolAddress((void**)&pX2,   g_X2);
    cudaGetSymbolAddress((void**)&pX2h,  g_X2h);
    cudaGetSymbolAddress((void**)&pQKVh, g_QKVh);
    cudaGetSymbolAddress((void**)&pCTXh, g_CTXh);
    cudaGetSymbolAddress((void**)&pTMPh, g_TMPh);
    cudaGetSymbolAddress((void**)&pPHI,  g_PHI);
    cudaGetSymbolAddress((void**)&pWh,   g_Wh);
    cudaGetSymbolAddress((void**)&pABb,  g_ABb);

    convw_kernel<<<W_TOTAL / 256, 256>>>(attn_in_w, attn_out_w, ff1_w, ff2_w, mlp1_w, mlp2_w, pWh);
    biasq_kernel<<<2, 192>>>(attn_in_b, pABb);

    // ===== q path =====
    proj_in_kernel<<<MQ, 128>>>(acc_Y, proj_in_w, proj_in_b, pX, pXh);
    hgemm_kernel<0,1><<<dim3(6, MQ / 128), 256>>>(pXh, pWh + W_ATTNIN, pABb, pQKVh, MQ, 384, 128);
    attn_mma_kernel<<<dim3(LL / 128, HH, BB), 256>>>(pQKVh, pCTXh);
    hgemm_ln_kernel<0><<<MQ / 128, 256>>>(pCTXh, pWh + W_ATTNOUT, attn_out_b, pX, ln1_g, ln1_b,
                                          pX2, pX2h, nullptr, nullptr, nullptr, MQ, 128);
    hgemm_kernel<1,1><<<dim3(4, MQ / 128), 256>>>(pX2h, pWh + W_FF1, ff1_b, pTMPh, MQ, 256, 128);
    hgemm_ln_kernel<1><<<MQ / 128, 256>>>(pTMPh, pWh + W_FF2, ff2_b, pX2, ln2_g, ln2_b,
                                          nullptr, nullptr, proj_out_w, proj_out_b, out, MQ, 256);

    // ===== phi path (fused) =====
    phi_fused_kernel<<<MP / 128, 256>>>(acc_Y, pWh + W_MLP1, mlp1_b, pWh + W_MLP2, mlp2_b,
                                        mlp3_w, mlp3_b, pPHI);
    norm_kernel<<<BB, 256>>>(pPHI, out + MQ * MODEN);
}